// round 2
// baseline (speedup 1.0000x reference)
#include <cuda_runtime.h>
#include <math.h>

// Problem shape (fixed by the dataset)
#define NB      4
#define SEQ     4096
#define DDIM    1024
#define HDIM    128
#define BSTOT   (NB * SEQ)          // 16384 rows

// ---------------- scratch (no cudaMalloc allowed) ----------------
__device__ float g_Q[BSTOT * HDIM];
__device__ float g_K[BSTOT * HDIM];
__device__ float g_V[BSTOT * HDIM];

// ======================= QKV projection =========================
// Out[16384,128] = X[16384,1024] @ W[1024,128], one of Q/K/V per blockIdx.y
__global__ __launch_bounds__(256) void proj_kernel(
    const float* __restrict__ X,
    const float* __restrict__ Wq,
    const float* __restrict__ Wk,
    const float* __restrict__ Wv)
{
    const float* W  = (blockIdx.y == 0) ? Wq : ((blockIdx.y == 1) ? Wk : Wv);
    float*       Out = (blockIdx.y == 0) ? g_Q : ((blockIdx.y == 1) ? g_K : g_V);

    __shared__ float Xs[64][16];
    __shared__ __align__(16) float Ws[16][128];

    const int tid  = threadIdx.x;
    const int row0 = blockIdx.x * 64;
    const int cg   = tid & 31;   // col group: cols cg*4 .. cg*4+3
    const int rg   = tid >> 5;   // row group: rows rg*8 .. rg*8+7

    float acc[8][4];
#pragma unroll
    for (int i = 0; i < 8; i++) {
        acc[i][0] = 0.f; acc[i][1] = 0.f; acc[i][2] = 0.f; acc[i][3] = 0.f;
    }

    for (int k0 = 0; k0 < DDIM; k0 += 16) {
        __syncthreads();
        {   // load X tile 64x16 (one float4 per thread)
            int r = tid >> 2, c = (tid & 3) << 2;
            float4 x = *(const float4*)(X + (size_t)(row0 + r) * DDIM + k0 + c);
            Xs[r][c] = x.x; Xs[r][c+1] = x.y; Xs[r][c+2] = x.z; Xs[r][c+3] = x.w;
        }
        {   // load W tile 16x128 (TWO float4 rows per thread: r and r+8)
            int r = tid >> 5, c = (tid & 31) << 2;
            *(float4*)(&Ws[r][c])     = *(const float4*)(W + (size_t)(k0 + r)     * HDIM + c);
            *(float4*)(&Ws[r + 8][c]) = *(const float4*)(W + (size_t)(k0 + r + 8) * HDIM + c);
        }
        __syncthreads();
#pragma unroll
        for (int kk = 0; kk < 16; kk++) {
            float4 bv = *(const float4*)(&Ws[kk][cg << 2]);
#pragma unroll
            for (int i = 0; i < 8; i++) {
                float a = Xs[(rg << 3) + i][kk];   // broadcast within warp
                acc[i][0] += a * bv.x;
                acc[i][1] += a * bv.y;
                acc[i][2] += a * bv.z;
                acc[i][3] += a * bv.w;
            }
        }
    }
#pragma unroll
    for (int i = 0; i < 8; i++) {
        float4 o = make_float4(acc[i][0], acc[i][1], acc[i][2], acc[i][3]);
        *(float4*)(Out + (size_t)(row0 + (rg << 3) + i) * HDIM + (cg << 2)) = o;
    }
}

// ======================= flash attention ========================
#define BM 64
#define BN 64
#define QS_STRIDE 132   // 16B-aligned rows, conflict-free
#define KS_STRIDE 132
#define VS_STRIDE 128
#define SS_STRIDE 68    // 16B-aligned rows, conflict-free scatter

#define SMEM_FLOATS (BM*QS_STRIDE + BN*KS_STRIDE + BN*VS_STRIDE + BM*SS_STRIDE)

__global__ __launch_bounds__(256) void attn_kernel(float* __restrict__ Out)
{
    extern __shared__ float sm[];
    float* Qs = sm;                         // [64][132], pre-scaled by 1/sqrt(128)
    float* Ks = Qs + BM * QS_STRIDE;        // [64][132]
    float* Vs = Ks + BN * KS_STRIDE;        // [64][128]
    float* Ss = Vs + BN * VS_STRIDE;        // [64][68]

    const int b     = blockIdx.y;
    const int qtile = (int)gridDim.x - 1 - (int)blockIdx.x;  // long blocks first
    const int qbase = qtile * BM;

    const float* Q = g_Q + (size_t)b * SEQ * HDIM;
    const float* K = g_K + (size_t)b * SEQ * HDIM;
    const float* V = g_V + (size_t)b * SEQ * HDIM;
    float*       O = Out + (size_t)b * SEQ * HDIM;

    const int tid = threadIdx.x;
    const float scale = 0.088388347648318447f;  // 1/sqrt(128)

    // Load Q tile (scaled)
    for (int i = tid; i < BM * HDIM / 4; i += 256) {
        int r = i >> 5, c = (i & 31) << 2;
        float4 q = *(const float4*)(Q + (size_t)(qbase + r) * HDIM + c);
        float* d = Qs + r * QS_STRIDE + c;
        d[0] = q.x * scale; d[1] = q.y * scale; d[2] = q.z * scale; d[3] = q.w * scale;
    }

    const int tg = tid & 15;          // column interleave group
    const int r0 = (tid >> 4) << 2;   // 4 rows per thread

    float m[4], l[4], acc[4][8];
#pragma unroll
    for (int i = 0; i < 4; i++) {
        m[i] = -INFINITY; l[i] = 0.f;
#pragma unroll
        for (int c = 0; c < 8; c++) acc[i][c] = 0.f;
    }

    for (int kt = 0; kt <= qtile; kt++) {
        const int kbase = kt * BN;
        __syncthreads();   // prior PV done; safe to overwrite K/V tiles
        for (int i = tid; i < BN * HDIM / 4; i += 256) {
            int r = i >> 5, c = (i & 31) << 2;
            float4 kv = *(const float4*)(K + (size_t)(kbase + r) * HDIM + c);
            float* kd = Ks + r * KS_STRIDE + c;
            kd[0] = kv.x; kd[1] = kv.y; kd[2] = kv.z; kd[3] = kv.w;
            *(float4*)(Vs + r * VS_STRIDE + c) =
                *(const float4*)(V + (size_t)(kbase + r) * HDIM + c);
        }
        __syncthreads();

        // -------- scores: s[i][c] = Q[r0+i] . K[tg+16c] --------
        float s[4][4];
#pragma unroll
        for (int i = 0; i < 4; i++)
#pragma unroll
            for (int c = 0; c < 4; c++) s[i][c] = 0.f;

        for (int k = 0; k < HDIM; k += 4) {
            float4 a0 = *(const float4*)(Qs + (r0 + 0) * QS_STRIDE + k);
            float4 a1 = *(const float4*)(Qs + (r0 + 1) * QS_STRIDE + k);
            float4 a2 = *(const float4*)(Qs + (r0 + 2) * QS_STRIDE + k);
            float4 a3 = *(const float4*)(Qs + (r0 + 3) * QS_STRIDE + k);
#pragma unroll
            for (int c = 0; c < 4; c++) {
                float4 bb = *(const float4*)(Ks + (tg + 16 * c) * KS_STRIDE + k);
                s[0][c] += a0.x * bb.x + a0.y * bb.y + a0.z * bb.z + a0.w * bb.w;
                s[1][c] += a1.x * bb.x + a1.y * bb.y + a1.z * bb.z + a1.w * bb.w;
                s[2][c] += a2.x * bb.x + a2.y * bb.y + a2.z * bb.z + a2.w * bb.w;
                s[3][c] += a3.x * bb.x + a3.y * bb.y + a3.z * bb.z + a3.w * bb.w;
            }
        }

        // -------- online softmax update --------
#pragma unroll
        for (int i = 0; i < 4; i++) {
            const int qrow = qbase + r0 + i;
            float tm = -INFINITY;
#pragma unroll
            for (int c = 0; c < 4; c++) {
                int kcol = kbase + tg + 16 * c;
                s[i][c] = (kcol <= qrow) ? s[i][c] : -INFINITY;
                tm = fmaxf(tm, s[i][c]);
            }
            tm = fmaxf(tm, __shfl_xor_sync(0xffffffffu, tm, 1));
            tm = fmaxf(tm, __shfl_xor_sync(0xffffffffu, tm, 2));
            tm = fmaxf(tm, __shfl_xor_sync(0xffffffffu, tm, 4));
            tm = fmaxf(tm, __shfl_xor_sync(0xffffffffu, tm, 8));

            float mn = fmaxf(m[i], tm);
            float alpha = __expf(m[i] - mn);
            m[i] = mn;

            float rs = 0.f;
#pragma unroll
            for (int c = 0; c < 4; c++) {
                float p = __expf(s[i][c] - mn);
                s[i][c] = p;
                rs += p;
            }
            rs += __shfl_xor_sync(0xffffffffu, rs, 1);
            rs += __shfl_xor_sync(0xffffffffu, rs, 2);
            rs += __shfl_xor_sync(0xffffffffu, rs, 4);
            rs += __shfl_xor_sync(0xffffffffu, rs, 8);
            l[i] = l[i] * alpha + rs;

#pragma unroll
            for (int c = 0; c < 8; c++) acc[i][c] *= alpha;
#pragma unroll
            for (int c = 0; c < 4; c++)
                Ss[(r0 + i) * SS_STRIDE + tg + 16 * c] = s[i][c];
        }
        __syncthreads();

        // -------- PV: acc[i][c] += P[r0+i][j] * V[j][tg+16c] --------
        for (int j = 0; j < BN; j += 4) {
            float4 p0 = *(const float4*)(Ss + (r0 + 0) * SS_STRIDE + j);
            float4 p1 = *(const float4*)(Ss + (r0 + 1) * SS_STRIDE + j);
            float4 p2 = *(const float4*)(Ss + (r0 + 2) * SS_STRIDE + j);
            float4 p3 = *(const float4*)(Ss + (r0 + 3) * SS_STRIDE + j);
#pragma unroll
            for (int jj = 0; jj < 4; jj++) {
                float q0 = (jj == 0) ? p0.x : (jj == 1) ? p0.y : (jj == 2) ? p0.z : p0.w;
                float q1 = (jj == 0) ? p1.x : (jj == 1) ? p1.y : (jj == 2) ? p1.z : p1.w;
                float q2 = (jj == 0) ? p2.x : (jj == 1) ? p2.y : (jj == 2) ? p2.z : p2.w;
                float q3 = (jj == 0) ? p3.x : (jj == 1) ? p3.y : (jj == 2) ? p3.z : p3.w;
#pragma unroll
                for (int c = 0; c < 8; c++) {
                    float v = Vs[(j + jj) * VS_STRIDE + tg + 16 * c];
                    acc[0][c] += q0 * v;
                    acc[1][c] += q1 * v;
                    acc[2][c] += q2 * v;
                    acc[3][c] += q3 * v;
                }
            }
        }
    }

    // -------- epilogue: normalize and store --------
#pragma unroll
    for (int i = 0; i < 4; i++) {
        float inv = 1.0f / l[i];
#pragma unroll
        for (int c = 0; c < 8; c++)
            O[(size_t)(qbase + r0 + i) * HDIM + tg + 16 * c] = acc[i][c] * inv;
    }
}

// =========================== launch =============================
extern "C" void kernel_launch(void* const* d_in, const int* in_sizes, int n_in,
                              void* d_out, int out_size)
{
    (void)in_sizes; (void)n_in; (void)out_size;
    const float* X  = (const float*)d_in[0];
    const float* Wq = (const float*)d_in[1];
    const float* Wk = (const float*)d_in[2];
    const float* Wv = (const float*)d_in[3];
    float* Out = (float*)d_out;

    // QKV projections: 256 row-tiles x 3 matrices
    dim3 pgrid(BSTOT / 64, 3);
    proj_kernel<<<pgrid, 256>>>(X, Wq, Wk, Wv);

    // Flash attention
    const int smem_bytes = SMEM_FLOATS * (int)sizeof(float);
    static int attr_set = 0;
    if (!attr_set) {
        cudaFuncSetAttribute(attn_kernel,
                             cudaFuncAttributeMaxDynamicSharedMemorySize,
                             smem_bytes);
        attr_set = 1;
    }
    dim3 agrid(SEQ / BM, NB);
    attn_kernel<<<agrid, 256, smem_bytes>>>(Out);
}

// round 3
// speedup vs baseline: 2.4149x; 2.4149x over previous
#include <cuda_runtime.h>
#include <math.h>
#include <stdint.h>

// Problem shape (fixed by the dataset)
#define NB      4
#define SEQ     4096
#define DDIM    1024
#define HDIM    128
#define BSTOT   (NB * SEQ)          // 16384 rows

// ---------------- scratch (no cudaMalloc allowed) ----------------
__device__ float g_Q[BSTOT * HDIM];
__device__ float g_K[BSTOT * HDIM];
__device__ float g_V[BSTOT * HDIM];

// ------------------- tf32 helpers -------------------
__device__ __forceinline__ uint32_t f2tf(float f) {
    uint32_t u; asm("cvt.rna.tf32.f32 %0, %1;" : "=r"(u) : "f"(f)); return u;
}
__device__ __forceinline__ uint4 f2tf4(float4 v) {
    return make_uint4(f2tf(v.x), f2tf(v.y), f2tf(v.z), f2tf(v.w));
}
// D += A(16x8, row) * B(8x8, col), fp32 accum
__device__ __forceinline__ void mma8(float* c, const uint32_t* a, const uint32_t* b) {
    asm volatile("mma.sync.aligned.m16n8k8.row.col.f32.tf32.tf32.f32 "
        "{%0,%1,%2,%3}, {%4,%5,%6,%7}, {%8,%9}, {%0,%1,%2,%3};"
        : "+f"(c[0]), "+f"(c[1]), "+f"(c[2]), "+f"(c[3])
        : "r"(a[0]), "r"(a[1]), "r"(a[2]), "r"(a[3]), "r"(b[0]), "r"(b[1]));
}
// Fragment layouts (m16n8k8.tf32), lane = g*4+tig, g=lane>>2, tig=lane&3:
//   A: a0=(g,tig) a1=(g+8,tig) a2=(g,tig+4) a3=(g+8,tig+4)
//   B: b0=(k=tig,n=g) b1=(k=tig+4,n=g)
//   C: c0=(g,2tig) c1=(g,2tig+1) c2=(g+8,2tig) c3=(g+8,2tig+1)

// ======================= QKV projection =========================
// Out[16384,128] = X[16384,1024] @ W[1024,128]
#define XS_STR 36
#define WS_STR 136
__global__ __launch_bounds__(256) void proj_kernel(
    const float* __restrict__ X,
    const float* __restrict__ Wq,
    const float* __restrict__ Wk,
    const float* __restrict__ Wv)
{
    const float* W   = (blockIdx.y == 0) ? Wq : ((blockIdx.y == 1) ? Wk : Wv);
    float*       Out = (blockIdx.y == 0) ? g_Q : ((blockIdx.y == 1) ? g_K : g_V);

    __shared__ uint32_t Xs[128 * XS_STR];   // 128x32 tf32 tile
    __shared__ uint32_t Ws[32 * WS_STR];    // 32x128 tf32 tile

    const int tid  = threadIdx.x;
    const int warp = tid >> 5, lane = tid & 31;
    const int g = lane >> 2, tig = lane & 3;
    const int wm = warp & 3;      // 4 warps along M (32 rows each)
    const int wn = warp >> 2;     // 2 warps along N (64 cols each)
    const int row0 = blockIdx.x * 128;

    float acc[2][8][4];
#pragma unroll
    for (int mi = 0; mi < 2; mi++)
#pragma unroll
        for (int ni = 0; ni < 8; ni++)
#pragma unroll
            for (int j = 0; j < 4; j++) acc[mi][ni][j] = 0.f;

    for (int k0 = 0; k0 < DDIM; k0 += 32) {
        __syncthreads();
        // X tile 128x32 (1024 float4)
        for (int i = tid; i < 1024; i += 256) {
            int r = i >> 3, c4 = i & 7;
            float4 v = *(const float4*)(X + (size_t)(row0 + r) * DDIM + k0 + c4 * 4);
            *(uint4*)(Xs + r * XS_STR + c4 * 4) = f2tf4(v);
        }
        // W tile 32x128 (1024 float4)
        for (int i = tid; i < 1024; i += 256) {
            int r = i >> 5, c4 = i & 31;
            float4 v = *(const float4*)(W + (size_t)(k0 + r) * HDIM + c4 * 4);
            *(uint4*)(Ws + r * WS_STR + c4 * 4) = f2tf4(v);
        }
        __syncthreads();
#pragma unroll
        for (int ks = 0; ks < 4; ks++) {
            const int kb = ks * 8;
            uint32_t a[2][4];
#pragma unroll
            for (int mi = 0; mi < 2; mi++) {
                const int rbm = wm * 32 + mi * 16;
                a[mi][0] = Xs[(rbm + g)     * XS_STR + kb + tig];
                a[mi][1] = Xs[(rbm + g + 8) * XS_STR + kb + tig];
                a[mi][2] = Xs[(rbm + g)     * XS_STR + kb + tig + 4];
                a[mi][3] = Xs[(rbm + g + 8) * XS_STR + kb + tig + 4];
            }
#pragma unroll
            for (int ni = 0; ni < 8; ni++) {
                uint32_t bb[2];
                const int col = wn * 64 + ni * 8 + g;
                bb[0] = Ws[(kb + tig)     * WS_STR + col];
                bb[1] = Ws[(kb + tig + 4) * WS_STR + col];
                mma8(acc[0][ni], a[0], bb);
                mma8(acc[1][ni], a[1], bb);
            }
        }
    }
#pragma unroll
    for (int mi = 0; mi < 2; mi++) {
        const int r = row0 + wm * 32 + mi * 16 + g;
#pragma unroll
        for (int ni = 0; ni < 8; ni++) {
            const int c = wn * 64 + ni * 8 + 2 * tig;
            *(float2*)(Out + (size_t)r       * HDIM + c) = make_float2(acc[mi][ni][0], acc[mi][ni][1]);
            *(float2*)(Out + (size_t)(r + 8) * HDIM + c) = make_float2(acc[mi][ni][2], acc[mi][ni][3]);
        }
    }
}

// ======================= flash attention ========================
// 128 threads = 4 warps; BM=BN=64; warp w owns rows w*16..w*16+15.
// Q lives in registers as prebuilt tf32 A-fragments.
#define KS_STR 132
#define VS_STR 136
#define SS_STR 68
#define ATT_SMEM ((64 * KS_STR + 64 * VS_STR + 64 * SS_STR) * 4)   // 86016 B

__global__ __launch_bounds__(128) void attn_kernel(float* __restrict__ Out)
{
    extern __shared__ uint32_t smu[];
    uint32_t* Ks = smu;                    // [64][132]
    uint32_t* Vs = Ks + 64 * KS_STR;       // [64][136]
    uint32_t* Ss = Vs + 64 * VS_STR;       // [64][68]

    const int tid  = threadIdx.x;
    const int warp = tid >> 5, lane = tid & 31;
    const int g = lane >> 2, tig = lane & 3;
    const int rb = warp * 16;

    const int b     = blockIdx.y;
    const int qtile = (int)gridDim.x - 1 - (int)blockIdx.x;   // long blocks first
    const int qbase = qtile * 64;

    const float* Q = g_Q + (size_t)b * SEQ * HDIM;
    const float* K = g_K + (size_t)b * SEQ * HDIM;
    const float* V = g_V + (size_t)b * SEQ * HDIM;
    float*       O = Out + (size_t)b * SEQ * HDIM;

    const float scale = 0.088388347648318447f;  // 1/sqrt(128)

    // Q -> register A-fragments (scaled), one-time
    uint32_t qa[16][4];
#pragma unroll
    for (int ks = 0; ks < 16; ks++) {
        const float* q0 = Q + (size_t)(qbase + rb + g)     * HDIM + ks * 8;
        const float* q1 = Q + (size_t)(qbase + rb + g + 8) * HDIM + ks * 8;
        qa[ks][0] = f2tf(q0[tig]     * scale);
        qa[ks][1] = f2tf(q1[tig]     * scale);
        qa[ks][2] = f2tf(q0[tig + 4] * scale);
        qa[ks][3] = f2tf(q1[tig + 4] * scale);
    }

    float o[16][4];
#pragma unroll
    for (int nt = 0; nt < 16; nt++)
#pragma unroll
        for (int j = 0; j < 4; j++) o[nt][j] = 0.f;
    float mr[2] = {-INFINITY, -INFINITY};
    float lr[2] = {0.f, 0.f};

    for (int kt = 0; kt <= qtile; kt++) {
        const int kbase = kt * 64;
        __syncthreads();   // prior iter's MMA reads done; safe to overwrite K/V
        for (int i = tid; i < 2048; i += 128) {
            int r = i >> 5, c4 = i & 31;
            float4 kv = *(const float4*)(K + (size_t)(kbase + r) * HDIM + c4 * 4);
            float4 vv = *(const float4*)(V + (size_t)(kbase + r) * HDIM + c4 * 4);
            *(uint4*)(Ks + r * KS_STR + c4 * 4) = f2tf4(kv);
            *(uint4*)(Vs + r * VS_STR + c4 * 4) = f2tf4(vv);
        }
        __syncthreads();

        // -------- S = Q K^T  (16x64 per warp) --------
        float s[8][4];
#pragma unroll
        for (int ni = 0; ni < 8; ni++)
#pragma unroll
            for (int j = 0; j < 4; j++) s[ni][j] = 0.f;

#pragma unroll
        for (int ks = 0; ks < 16; ks++) {
            const int kb = ks * 8;
#pragma unroll
            for (int ni = 0; ni < 8; ni++) {
                uint32_t bb[2];
                bb[0] = Ks[(ni * 8 + g) * KS_STR + kb + tig];
                bb[1] = Ks[(ni * 8 + g) * KS_STR + kb + tig + 4];
                mma8(s[ni], qa[ks], bb);
            }
        }

        // -------- causal mask (diagonal tile only) --------
        if (kt == qtile) {
            const int r0l = rb + g, r1l = rb + g + 8;
#pragma unroll
            for (int ni = 0; ni < 8; ni++) {
                const int c = ni * 8 + 2 * tig;
                s[ni][0] = (c     <= r0l) ? s[ni][0] : -INFINITY;
                s[ni][1] = (c + 1 <= r0l) ? s[ni][1] : -INFINITY;
                s[ni][2] = (c     <= r1l) ? s[ni][2] : -INFINITY;
                s[ni][3] = (c + 1 <= r1l) ? s[ni][3] : -INFINITY;
            }
        }

        // -------- online softmax (per row-half, quad reduce) --------
#pragma unroll
        for (int h = 0; h < 2; h++) {
            float tm = -INFINITY;
#pragma unroll
            for (int ni = 0; ni < 8; ni++)
                tm = fmaxf(tm, fmaxf(s[ni][2 * h], s[ni][2 * h + 1]));
            tm = fmaxf(tm, __shfl_xor_sync(0xffffffffu, tm, 1));
            tm = fmaxf(tm, __shfl_xor_sync(0xffffffffu, tm, 2));

            const float mn = fmaxf(mr[h], tm);
            const float alpha = __expf(mr[h] - mn);
            mr[h] = mn;

            float rs = 0.f;
#pragma unroll
            for (int ni = 0; ni < 8; ni++) {
                float p0 = __expf(s[ni][2 * h]     - mn);
                float p1 = __expf(s[ni][2 * h + 1] - mn);
                s[ni][2 * h] = p0; s[ni][2 * h + 1] = p1;
                rs += p0 + p1;
            }
            rs += __shfl_xor_sync(0xffffffffu, rs, 1);
            rs += __shfl_xor_sync(0xffffffffu, rs, 2);
            lr[h] = lr[h] * alpha + rs;

#pragma unroll
            for (int nt = 0; nt < 16; nt++) {
                o[nt][2 * h]     *= alpha;
                o[nt][2 * h + 1] *= alpha;
            }
        }

        // -------- P to smem (own 16-row slab; warp-local) --------
        __syncwarp();
#pragma unroll
        for (int ni = 0; ni < 8; ni++) {
            const int c = ni * 8 + 2 * tig;
            Ss[(rb + g)     * SS_STR + c]     = f2tf(s[ni][0]);
            Ss[(rb + g)     * SS_STR + c + 1] = f2tf(s[ni][1]);
            Ss[(rb + g + 8) * SS_STR + c]     = f2tf(s[ni][2]);
            Ss[(rb + g + 8) * SS_STR + c + 1] = f2tf(s[ni][3]);
        }
        __syncwarp();

        // -------- O += P V  (16x128 per warp) --------
#pragma unroll
        for (int js = 0; js < 8; js++) {
            const int jb = js * 8;
            uint32_t pa[4];
            pa[0] = Ss[(rb + g)     * SS_STR + jb + tig];
            pa[1] = Ss[(rb + g + 8) * SS_STR + jb + tig];
            pa[2] = Ss[(rb + g)     * SS_STR + jb + tig + 4];
            pa[3] = Ss[(rb + g + 8) * SS_STR + jb + tig + 4];
#pragma unroll
            for (int nt = 0; nt < 16; nt++) {
                uint32_t bb[2];
                bb[0] = Vs[(jb + tig)     * VS_STR + nt * 8 + g];
                bb[1] = Vs[(jb + tig + 4) * VS_STR + nt * 8 + g];
                mma8(o[nt], pa, bb);
            }
        }
    }

    // -------- epilogue --------
    const float inv0 = 1.0f / lr[0], inv1 = 1.0f / lr[1];
#pragma unroll
    for (int nt = 0; nt < 16; nt++) {
        const int c = nt * 8 + 2 * tig;
        *(float2*)(O + (size_t)(qbase + rb + g)     * HDIM + c) =
            make_float2(o[nt][0] * inv0, o[nt][1] * inv0);
        *(float2*)(O + (size_t)(qbase + rb + g + 8) * HDIM + c) =
            make_float2(o[nt][2] * inv1, o[nt][3] * inv1);
    }
}

// =========================== launch =============================
extern "C" void kernel_launch(void* const* d_in, const int* in_sizes, int n_in,
                              void* d_out, int out_size)
{
    (void)in_sizes; (void)n_in; (void)out_size;
    const float* X  = (const float*)d_in[0];
    const float* Wq = (const float*)d_in[1];
    const float* Wk = (const float*)d_in[2];
    const float* Wv = (const float*)d_in[3];
    float* Out = (float*)d_out;

    dim3 pgrid(BSTOT / 128, 3);
    proj_kernel<<<pgrid, 256>>>(X, Wq, Wk, Wv);

    static int attr_set = 0;
    if (!attr_set) {
        cudaFuncSetAttribute(attn_kernel,
                             cudaFuncAttributeMaxDynamicSharedMemorySize,
                             ATT_SMEM);
        attr_set = 1;
    }
    dim3 agrid(SEQ / 64, NB);
    attn_kernel<<<agrid, 128, ATT_SMEM>>>(Out);
}

// round 4
// speedup vs baseline: 3.1693x; 1.3124x over previous
#include <cuda_runtime.h>
#include <math.h>
#include <stdint.h>

// Problem shape (fixed by the dataset)
#define NB      4
#define SEQ     4096
#define DDIM    1024
#define HDIM    128
#define BSTOT   (NB * SEQ)          // 16384 rows

// ---------------- scratch (no cudaMalloc allowed) ----------------
__device__ float g_Q[BSTOT * HDIM];
__device__ float g_K[BSTOT * HDIM];
__device__ float g_V[BSTOT * HDIM];

// ------------------- helpers -------------------
__device__ __forceinline__ uint32_t f2tf(float f) {
    uint32_t u; asm("cvt.rna.tf32.f32 %0, %1;" : "=r"(u) : "f"(f)); return u;
}
// D += A(16x8, row) * B(8x8, col), fp32 accum
__device__ __forceinline__ void mma8(float* c, const uint32_t* a, const uint32_t* b) {
    asm volatile("mma.sync.aligned.m16n8k8.row.col.f32.tf32.tf32.f32 "
        "{%0,%1,%2,%3}, {%4,%5,%6,%7}, {%8,%9}, {%0,%1,%2,%3};"
        : "+f"(c[0]), "+f"(c[1]), "+f"(c[2]), "+f"(c[3])
        : "r"(a[0]), "r"(a[1]), "r"(a[2]), "r"(a[3]), "r"(b[0]), "r"(b[1]));
}
// Fragment layouts (m16n8k8.tf32), lane = g*4+tig, g=lane>>2, tig=lane&3:
//   A: a0=(g,tig) a1=(g+8,tig) a2=(g,tig+4) a3=(g+8,tig+4)
//   B: b0=(k=tig,n=g) b1=(k=tig+4,n=g)
//   C: c0=(g,2tig) c1=(g,2tig+1) c2=(g+8,2tig) c3=(g+8,2tig+1)

__device__ __forceinline__ uint32_t smaddr(const void* p) {
    return (uint32_t)__cvta_generic_to_shared(p);
}
__device__ __forceinline__ void cp16(uint32_t s, const void* g) {
    asm volatile("cp.async.ca.shared.global [%0], [%1], 16;" :: "r"(s), "l"(g));
}
__device__ __forceinline__ void cp_commit() {
    asm volatile("cp.async.commit_group;");
}
template <int N>
__device__ __forceinline__ void cp_wait() {
    asm volatile("cp.async.wait_group %0;" :: "n"(N));
}

// ======================= QKV projection =========================
// Out[16384,128] = X[16384,1024] @ W[1024,128]; 2-stage cp.async pipeline.
#define XS_STR 36
#define WS_STR 136
#define PROJ_SMEM ((2 * 128 * XS_STR + 2 * 32 * WS_STR) * 4)   // 71680 B

__global__ __launch_bounds__(256, 2) void proj_kernel(
    const float* __restrict__ X,
    const float* __restrict__ Wq,
    const float* __restrict__ Wk,
    const float* __restrict__ Wv)
{
    const float* W   = (blockIdx.y == 0) ? Wq : ((blockIdx.y == 1) ? Wk : Wv);
    float*       Out = (blockIdx.y == 0) ? g_Q : ((blockIdx.y == 1) ? g_K : g_V);

    extern __shared__ float psm[];
    float* Xb = psm;                        // [2][128*36]
    float* Wb = psm + 2 * 128 * XS_STR;     // [2][32*136]

    const int tid  = threadIdx.x;
    const int warp = tid >> 5, lane = tid & 31;
    const int g = lane >> 2, tig = lane & 3;
    const int wm = warp & 3;      // 4 warps along M (32 rows each)
    const int wn = warp >> 2;     // 2 warps along N (64 cols each)
    const int row0 = blockIdx.x * 128;

    // stage loader: X tile 128x32, W tile 32x128 at k0, into buf s
    auto issue_stage = [&](int k0, int s) {
        float* Xd = Xb + s * 128 * XS_STR;
        float* Wd = Wb + s * 32 * WS_STR;
#pragma unroll
        for (int c = tid; c < 1024; c += 256) {
            int r = c >> 3, c4 = c & 7;
            cp16(smaddr(Xd + r * XS_STR + c4 * 4),
                 X + (size_t)(row0 + r) * DDIM + k0 + c4 * 4);
        }
#pragma unroll
        for (int c = tid; c < 1024; c += 256) {
            int r = c >> 5, c4 = c & 31;
            cp16(smaddr(Wd + r * WS_STR + c4 * 4),
                 W + (size_t)(k0 + r) * HDIM + c4 * 4);
        }
        cp_commit();
    };

    float acc[2][8][4];
#pragma unroll
    for (int mi = 0; mi < 2; mi++)
#pragma unroll
        for (int ni = 0; ni < 8; ni++)
#pragma unroll
            for (int j = 0; j < 4; j++) acc[mi][ni][j] = 0.f;

    issue_stage(0, 0);

    for (int ki = 0; ki < 32; ki++) {
        if (ki < 31) { issue_stage((ki + 1) * 32, (ki + 1) & 1); cp_wait<1>(); }
        else         { cp_wait<0>(); }
        __syncthreads();

        const float* Xs = Xb + (ki & 1) * 128 * XS_STR;
        const float* Ws = Wb + (ki & 1) * 32 * WS_STR;
#pragma unroll
        for (int ks = 0; ks < 4; ks++) {
            const int kb = ks * 8;
            uint32_t a[2][4];
#pragma unroll
            for (int mi = 0; mi < 2; mi++) {
                const int rbm = wm * 32 + mi * 16;
                a[mi][0] = f2tf(Xs[(rbm + g)     * XS_STR + kb + tig]);
                a[mi][1] = f2tf(Xs[(rbm + g + 8) * XS_STR + kb + tig]);
                a[mi][2] = f2tf(Xs[(rbm + g)     * XS_STR + kb + tig + 4]);
                a[mi][3] = f2tf(Xs[(rbm + g + 8) * XS_STR + kb + tig + 4]);
            }
#pragma unroll
            for (int ni = 0; ni < 8; ni++) {
                uint32_t bb[2];
                const int col = wn * 64 + ni * 8 + g;
                bb[0] = f2tf(Ws[(kb + tig)     * WS_STR + col]);
                bb[1] = f2tf(Ws[(kb + tig + 4) * WS_STR + col]);
                mma8(acc[0][ni], a[0], bb);
                mma8(acc[1][ni], a[1], bb);
            }
        }
        __syncthreads();
    }

#pragma unroll
    for (int mi = 0; mi < 2; mi++) {
        const int r = row0 + wm * 32 + mi * 16 + g;
#pragma unroll
        for (int ni = 0; ni < 8; ni++) {
            const int c = wn * 64 + ni * 8 + 2 * tig;
            *(float2*)(Out + (size_t)r       * HDIM + c) = make_float2(acc[mi][ni][0], acc[mi][ni][1]);
            *(float2*)(Out + (size_t)(r + 8) * HDIM + c) = make_float2(acc[mi][ni][2], acc[mi][ni][3]);
        }
    }
}

// ======================= flash attention ========================
// 128 threads = 4 warps; BM=BN=64; warp w owns rows w*16..w*16+15.
// Each CTA processes the tile pair (63-x, x): uniform 65 steps.
// K double-buffered via cp.async, V single-buffered (latency hidden by QK).
#define KS_STR 132
#define VS_STR 136
#define ATT_SMEM ((2 * 64 * KS_STR + 64 * VS_STR) * 4)   // 102400 B

__global__ __launch_bounds__(128) void attn_kernel(float* __restrict__ Out)
{
    extern __shared__ float asm_[];
    float* Kb = asm_;                       // [2][64*132]
    float* Vb = asm_ + 2 * 64 * KS_STR;     // [64*136]

    const int tid  = threadIdx.x;
    const int warp = tid >> 5, lane = tid & 31;
    const int g = lane >> 2, tig = lane & 3;
    const int rb = warp * 16;
    const int b  = blockIdx.y;

    const float* Q = g_Q + (size_t)b * SEQ * HDIM;
    const float* K = g_K + (size_t)b * SEQ * HDIM;
    const float* V = g_V + (size_t)b * SEQ * HDIM;
    float*       O = Out + (size_t)b * SEQ * HDIM;

    const float scale = 0.088388347648318447f;  // 1/sqrt(128)

    auto issue_K = [&](int kbase, int s) {
        float* Kd = Kb + s * 64 * KS_STR;
#pragma unroll
        for (int c = tid; c < 2048; c += 128) {
            int r = c >> 5, c4 = c & 31;
            cp16(smaddr(Kd + r * KS_STR + c4 * 4),
                 K + (size_t)(kbase + r) * HDIM + c4 * 4);
        }
        cp_commit();
    };
    auto issue_V = [&](int kbase) {
#pragma unroll
        for (int c = tid; c < 2048; c += 128) {
            int r = c >> 5, c4 = c & 31;
            cp16(smaddr(Vb + r * VS_STR + c4 * 4),
                 V + (size_t)(kbase + r) * HDIM + c4 * 4);
        }
        cp_commit();
    };

    for (int half = 0; half < 2; half++) {
        const int qtile = half ? (int)blockIdx.x : 63 - (int)blockIdx.x;
        const int qbase = qtile * 64;

        // Q -> register A-fragments (scaled)
        uint32_t qa[16][4];
#pragma unroll
        for (int ks = 0; ks < 16; ks++) {
            const float* q0 = Q + (size_t)(qbase + rb + g)     * HDIM + ks * 8;
            const float* q1 = Q + (size_t)(qbase + rb + g + 8) * HDIM + ks * 8;
            qa[ks][0] = f2tf(q0[tig]     * scale);
            qa[ks][1] = f2tf(q1[tig]     * scale);
            qa[ks][2] = f2tf(q0[tig + 4] * scale);
            qa[ks][3] = f2tf(q1[tig + 4] * scale);
        }

        float o[16][4];
#pragma unroll
        for (int nt = 0; nt < 16; nt++)
#pragma unroll
            for (int j = 0; j < 4; j++) o[nt][j] = 0.f;
        float mr[2] = {-INFINITY, -INFINITY};
        float lr[2] = {0.f, 0.f};

        // prologue
        issue_K(0, 0);
        issue_V(0);
        cp_wait<1>();        // K(0) ready
        __syncthreads();

        for (int kt = 0; kt <= qtile; kt++) {
            const int nxt = (kt + 1 <= qtile) ? (kt + 1) * 64 : qtile * 64;
            issue_K(nxt, (kt + 1) & 1);           // overlaps with QK below

            const float* Ks = Kb + (kt & 1) * 64 * KS_STR;

            // -------- S = Q K^T  (16x64 per warp) --------
            float s[8][4];
#pragma unroll
            for (int ni = 0; ni < 8; ni++)
#pragma unroll
                for (int j = 0; j < 4; j++) s[ni][j] = 0.f;

#pragma unroll
            for (int ks = 0; ks < 16; ks++) {
                const int kb = ks * 8;
#pragma unroll
                for (int ni = 0; ni < 8; ni++) {
                    uint32_t bb[2];
                    bb[0] = f2tf(Ks[(ni * 8 + g) * KS_STR + kb + tig]);
                    bb[1] = f2tf(Ks[(ni * 8 + g) * KS_STR + kb + tig + 4]);
                    mma8(s[ni], qa[ks], bb);
                }
            }

            // -------- causal mask (diagonal tile only) --------
            if (kt == qtile) {
                const int r0l = rb + g, r1l = rb + g + 8;
#pragma unroll
                for (int ni = 0; ni < 8; ni++) {
                    const int c = ni * 8 + 2 * tig;
                    s[ni][0] = (c     <= r0l) ? s[ni][0] : -INFINITY;
                    s[ni][1] = (c + 1 <= r0l) ? s[ni][1] : -INFINITY;
                    s[ni][2] = (c     <= r1l) ? s[ni][2] : -INFINITY;
                    s[ni][3] = (c + 1 <= r1l) ? s[ni][3] : -INFINITY;
                }
            }

            // -------- online softmax (per row-half, quad reduce) --------
#pragma unroll
            for (int h = 0; h < 2; h++) {
                float tm = -INFINITY;
#pragma unroll
                for (int ni = 0; ni < 8; ni++)
                    tm = fmaxf(tm, fmaxf(s[ni][2 * h], s[ni][2 * h + 1]));
                tm = fmaxf(tm, __shfl_xor_sync(0xffffffffu, tm, 1));
                tm = fmaxf(tm, __shfl_xor_sync(0xffffffffu, tm, 2));

                const float mn = fmaxf(mr[h], tm);
                const float alpha = __expf(mr[h] - mn);
                mr[h] = mn;

                float rs = 0.f;
#pragma unroll
                for (int ni = 0; ni < 8; ni++) {
                    float p0 = __expf(s[ni][2 * h]     - mn);
                    float p1 = __expf(s[ni][2 * h + 1] - mn);
                    s[ni][2 * h] = p0; s[ni][2 * h + 1] = p1;
                    rs += p0 + p1;
                }
                rs += __shfl_xor_sync(0xffffffffu, rs, 1);
                rs += __shfl_xor_sync(0xffffffffu, rs, 2);
                lr[h] = lr[h] * alpha + rs;

#pragma unroll
                for (int nt = 0; nt < 16; nt++) {
                    o[nt][2 * h]     *= alpha;
                    o[nt][2 * h + 1] *= alpha;
                }
            }
            // P -> tf32 bits (kept as float regs for shuffle)
#pragma unroll
            for (int ni = 0; ni < 8; ni++)
#pragma unroll
                for (int j = 0; j < 4; j++)
                    s[ni][j] = __uint_as_float(f2tf(s[ni][j]));

            // -------- wait V(kt), all threads --------
            cp_wait<1>();
            __syncthreads();

            // -------- O += P V  (16x128 per warp); P A-frags via shuffles ----
            const int s1 = (lane & 0x1c) | (tig >> 1);
            const bool odd = (tig & 1);
#pragma unroll
            for (int js = 0; js < 8; js++) {
                float v00 = __shfl_sync(0xffffffffu, s[js][0], s1);
                float v01 = __shfl_sync(0xffffffffu, s[js][1], s1);
                float v10 = __shfl_sync(0xffffffffu, s[js][2], s1);
                float v11 = __shfl_sync(0xffffffffu, s[js][3], s1);
                float v20 = __shfl_sync(0xffffffffu, s[js][0], s1 + 2);
                float v21 = __shfl_sync(0xffffffffu, s[js][1], s1 + 2);
                float v30 = __shfl_sync(0xffffffffu, s[js][2], s1 + 2);
                float v31 = __shfl_sync(0xffffffffu, s[js][3], s1 + 2);
                uint32_t pa[4];
                pa[0] = __float_as_uint(odd ? v01 : v00);
                pa[1] = __float_as_uint(odd ? v11 : v10);
                pa[2] = __float_as_uint(odd ? v21 : v20);
                pa[3] = __float_as_uint(odd ? v31 : v30);
                const int jb = js * 8;
#pragma unroll
                for (int nt = 0; nt < 16; nt++) {
                    uint32_t bb[2];
                    bb[0] = f2tf(Vb[(jb + tig)     * VS_STR + nt * 8 + g]);
                    bb[1] = f2tf(Vb[(jb + tig + 4) * VS_STR + nt * 8 + g]);
                    mma8(o[nt], pa, bb);
                }
            }

            // -------- prefetch V(kt+1) after all PV reads done --------
            __syncthreads();
            issue_V(nxt);

            // -------- K(kt+1) ready for next iter --------
            cp_wait<1>();
            __syncthreads();
        }

        cp_wait<0>();
        __syncthreads();   // drain before next half reuses buffers

        // -------- epilogue --------
        const float inv0 = 1.0f / lr[0], inv1 = 1.0f / lr[1];
#pragma unroll
        for (int nt = 0; nt < 16; nt++) {
            const int c = nt * 8 + 2 * tig;
            *(float2*)(O + (size_t)(qbase + rb + g)     * HDIM + c) =
                make_float2(o[nt][0] * inv0, o[nt][1] * inv0);
            *(float2*)(O + (size_t)(qbase + rb + g + 8) * HDIM + c) =
                make_float2(o[nt][2] * inv1, o[nt][3] * inv1);
        }
    }
}

// =========================== launch =============================
extern "C" void kernel_launch(void* const* d_in, const int* in_sizes, int n_in,
                              void* d_out, int out_size)
{
    (void)in_sizes; (void)n_in; (void)out_size;
    const float* X  = (const float*)d_in[0];
    const float* Wq = (const float*)d_in[1];
    const float* Wk = (const float*)d_in[2];
    const float* Wv = (const float*)d_in[3];
    float* Out = (float*)d_out;

    static int attr_set = 0;
    if (!attr_set) {
        cudaFuncSetAttribute(proj_kernel,
                             cudaFuncAttributeMaxDynamicSharedMemorySize,
                             PROJ_SMEM);
        cudaFuncSetAttribute(attn_kernel,
                             cudaFuncAttributeMaxDynamicSharedMemorySize,
                             ATT_SMEM);
        attr_set = 1;
    }

    dim3 pgrid(BSTOT / 128, 3);
    proj_kernel<<<pgrid, 256, PROJ_SMEM>>>(X, Wq, Wk, Wv);

    dim3 agrid(32, NB);   // tile pairs (63-x, x) x 4 batches
    attn_kernel<<<agrid, 128, ATT_SMEM>>>(Out);
}

// round 5
// speedup vs baseline: 3.6958x; 1.1661x over previous
#include <cuda_runtime.h>
#include <math.h>
#include <stdint.h>

// Problem shape (fixed by the dataset)
#define NB      4
#define SEQ     4096
#define DDIM    1024
#define HDIM    128
#define BSTOT   (NB * SEQ)          // 16384 rows

// ---------------- scratch (no cudaMalloc allowed) ----------------
// Q is pre-scaled by 1/sqrt(128) and tf32-rounded; K/V tf32-rounded.
__device__ float g_Q[BSTOT * HDIM];
__device__ float g_K[BSTOT * HDIM];
__device__ float g_V[BSTOT * HDIM];

// ------------------- helpers -------------------
__device__ __forceinline__ uint32_t f2tf(float f) {
    uint32_t u; asm("cvt.rna.tf32.f32 %0, %1;" : "=r"(u) : "f"(f)); return u;
}
// D += A(16x8, row) * B(8x8, col), fp32 accum
__device__ __forceinline__ void mma8(float* c, const uint32_t* a, const uint32_t* b) {
    asm volatile("mma.sync.aligned.m16n8k8.row.col.f32.tf32.tf32.f32 "
        "{%0,%1,%2,%3}, {%4,%5,%6,%7}, {%8,%9}, {%0,%1,%2,%3};"
        : "+f"(c[0]), "+f"(c[1]), "+f"(c[2]), "+f"(c[3])
        : "r"(a[0]), "r"(a[1]), "r"(a[2]), "r"(a[3]), "r"(b[0]), "r"(b[1]));
}
// Fragment layouts (m16n8k8.tf32), lane = g*4+tig, g=lane>>2, tig=lane&3:
//   A: a0=(g,tig) a1=(g+8,tig) a2=(g,tig+4) a3=(g+8,tig+4)
//   B: b0=(k=tig,n=g) b1=(k=tig+4,n=g)
//   C: c0=(g,2tig) c1=(g,2tig+1) c2=(g+8,2tig) c3=(g+8,2tig+1)

__device__ __forceinline__ uint32_t smaddr(const void* p) {
    return (uint32_t)__cvta_generic_to_shared(p);
}
__device__ __forceinline__ void cp16(uint32_t s, const void* g) {
    asm volatile("cp.async.ca.shared.global [%0], [%1], 16;" :: "r"(s), "l"(g));
}
__device__ __forceinline__ void cp_commit() {
    asm volatile("cp.async.commit_group;");
}
template <int N>
__device__ __forceinline__ void cp_wait() {
    asm volatile("cp.async.wait_group %0;" :: "n"(N));
}

// ======================= QKV projection =========================
// Out[16384,128] = X[16384,1024] @ W[1024,128]; 2-stage cp.async pipeline.
// Epilogue writes tf32-rounded values (Q additionally pre-scaled).
#define XS_STR 36
#define WS_STR 136
#define PROJ_SMEM ((2 * 128 * XS_STR + 2 * 32 * WS_STR) * 4)   // 71680 B

__global__ __launch_bounds__(256, 2) void proj_kernel(
    const float* __restrict__ X,
    const float* __restrict__ Wq,
    const float* __restrict__ Wk,
    const float* __restrict__ Wv)
{
    const float* W   = (blockIdx.y == 0) ? Wq : ((blockIdx.y == 1) ? Wk : Wv);
    float*       Out = (blockIdx.y == 0) ? g_Q : ((blockIdx.y == 1) ? g_K : g_V);

    extern __shared__ float psm[];
    float* Xb = psm;                        // [2][128*36]
    float* Wb = psm + 2 * 128 * XS_STR;     // [2][32*136]

    const int tid  = threadIdx.x;
    const int warp = tid >> 5, lane = tid & 31;
    const int g = lane >> 2, tig = lane & 3;
    const int wm = warp & 3;      // 4 warps along M (32 rows each)
    const int wn = warp >> 2;     // 2 warps along N (64 cols each)
    const int row0 = blockIdx.x * 128;

    auto issue_stage = [&](int k0, int s) {
        float* Xd = Xb + s * 128 * XS_STR;
        float* Wd = Wb + s * 32 * WS_STR;
#pragma unroll
        for (int c = tid; c < 1024; c += 256) {
            int r = c >> 3, c4 = c & 7;
            cp16(smaddr(Xd + r * XS_STR + c4 * 4),
                 X + (size_t)(row0 + r) * DDIM + k0 + c4 * 4);
        }
#pragma unroll
        for (int c = tid; c < 1024; c += 256) {
            int r = c >> 5, c4 = c & 31;
            cp16(smaddr(Wd + r * WS_STR + c4 * 4),
                 W + (size_t)(k0 + r) * HDIM + c4 * 4);
        }
        cp_commit();
    };

    float acc[2][8][4];
#pragma unroll
    for (int mi = 0; mi < 2; mi++)
#pragma unroll
        for (int ni = 0; ni < 8; ni++)
#pragma unroll
            for (int j = 0; j < 4; j++) acc[mi][ni][j] = 0.f;

    issue_stage(0, 0);

    for (int ki = 0; ki < 32; ki++) {
        if (ki < 31) { issue_stage((ki + 1) * 32, (ki + 1) & 1); cp_wait<1>(); }
        else         { cp_wait<0>(); }
        __syncthreads();

        const float* Xs = Xb + (ki & 1) * 128 * XS_STR;
        const float* Ws = Wb + (ki & 1) * 32 * WS_STR;
#pragma unroll
        for (int ks = 0; ks < 4; ks++) {
            const int kb = ks * 8;
            uint32_t a[2][4];
#pragma unroll
            for (int mi = 0; mi < 2; mi++) {
                const int rbm = wm * 32 + mi * 16;
                a[mi][0] = f2tf(Xs[(rbm + g)     * XS_STR + kb + tig]);
                a[mi][1] = f2tf(Xs[(rbm + g + 8) * XS_STR + kb + tig]);
                a[mi][2] = f2tf(Xs[(rbm + g)     * XS_STR + kb + tig + 4]);
                a[mi][3] = f2tf(Xs[(rbm + g + 8) * XS_STR + kb + tig + 4]);
            }
#pragma unroll
            for (int ni = 0; ni < 8; ni++) {
                uint32_t bb[2];
                const int col = wn * 64 + ni * 8 + g;
                bb[0] = f2tf(Ws[(kb + tig)     * WS_STR + col]);
                bb[1] = f2tf(Ws[(kb + tig + 4) * WS_STR + col]);
                mma8(acc[0][ni], a[0], bb);
                mma8(acc[1][ni], a[1], bb);
            }
        }
        __syncthreads();
    }

    // epilogue: tf32-round (Q pre-scaled) so attention can skip all cvts
    const float osc = (blockIdx.y == 0) ? 0.088388347648318447f : 1.0f;
#pragma unroll
    for (int mi = 0; mi < 2; mi++) {
        const int r = row0 + wm * 32 + mi * 16 + g;
#pragma unroll
        for (int ni = 0; ni < 8; ni++) {
            const int c = wn * 64 + ni * 8 + 2 * tig;
            *(float2*)(Out + (size_t)r       * HDIM + c) = make_float2(
                __uint_as_float(f2tf(acc[mi][ni][0] * osc)),
                __uint_as_float(f2tf(acc[mi][ni][1] * osc)));
            *(float2*)(Out + (size_t)(r + 8) * HDIM + c) = make_float2(
                __uint_as_float(f2tf(acc[mi][ni][2] * osc)),
                __uint_as_float(f2tf(acc[mi][ni][3] * osc)));
        }
    }
}

// ======================= flash attention ========================
// 128 threads = 4 warps; BM=BN=64; warp w owns rows w*16..w*16+15.
// One qtile per CTA, longest first; 2 CTAs co-resident per SM.
// K double-buffered via cp.async, V single-buffered (latency hidden by QK).
#define KS_STR 132
#define VS_STR 136
#define ATT_SMEM ((2 * 64 * KS_STR + 64 * VS_STR) * 4)   // 102400 B

__global__ __launch_bounds__(128) void attn_kernel(float* __restrict__ Out)
{
    extern __shared__ float asm_[];
    float* Kb = asm_;                       // [2][64*132]
    float* Vb = asm_ + 2 * 64 * KS_STR;     // [64*136]

    const int tid  = threadIdx.x;
    const int warp = tid >> 5, lane = tid & 31;
    const int g = lane >> 2, tig = lane & 3;
    const int rb = warp * 16;
    const int b  = blockIdx.y;

    const float* Q = g_Q + (size_t)b * SEQ * HDIM;
    const float* K = g_K + (size_t)b * SEQ * HDIM;
    const float* V = g_V + (size_t)b * SEQ * HDIM;
    float*       O = Out + (size_t)b * SEQ * HDIM;

    const int qtile = 63 - (int)blockIdx.x;   // longest job first
    const int qbase = qtile * 64;

    auto issue_K = [&](int kbase, int s) {
        float* Kd = Kb + s * 64 * KS_STR;
#pragma unroll
        for (int c = tid; c < 2048; c += 128) {
            int r = c >> 5, c4 = c & 31;
            cp16(smaddr(Kd + r * KS_STR + c4 * 4),
                 K + (size_t)(kbase + r) * HDIM + c4 * 4);
        }
        cp_commit();
    };
    auto issue_V = [&](int kbase) {
#pragma unroll
        for (int c = tid; c < 2048; c += 128) {
            int r = c >> 5, c4 = c & 31;
            cp16(smaddr(Vb + r * VS_STR + c4 * 4),
                 V + (size_t)(kbase + r) * HDIM + c4 * 4);
        }
        cp_commit();
    };

    // Q -> register A-fragments (already scaled + tf32-rounded in gmem)
    uint32_t qa[16][4];
#pragma unroll
    for (int ks = 0; ks < 16; ks++) {
        const uint32_t* q0 = (const uint32_t*)(Q + (size_t)(qbase + rb + g)     * HDIM + ks * 8);
        const uint32_t* q1 = (const uint32_t*)(Q + (size_t)(qbase + rb + g + 8) * HDIM + ks * 8);
        qa[ks][0] = q0[tig];
        qa[ks][1] = q1[tig];
        qa[ks][2] = q0[tig + 4];
        qa[ks][3] = q1[tig + 4];
    }

    float o[16][4];
#pragma unroll
    for (int nt = 0; nt < 16; nt++)
#pragma unroll
        for (int j = 0; j < 4; j++) o[nt][j] = 0.f;
    float mr[2] = {-INFINITY, -INFINITY};
    float lr[2] = {0.f, 0.f};

    // prologue
    issue_K(0, 0);
    issue_V(0);
    cp_wait<1>();        // K(0) ready
    __syncthreads();

    for (int kt = 0; kt <= qtile; kt++) {
        const int nxt = (kt + 1 <= qtile) ? (kt + 1) * 64 : qtile * 64;
        issue_K(nxt, (kt + 1) & 1);           // overlaps with QK below

        const uint32_t* Ks = (const uint32_t*)(Kb + (kt & 1) * 64 * KS_STR);

        // -------- S = Q K^T  (16x64 per warp) --------
        float s[8][4];
#pragma unroll
        for (int ni = 0; ni < 8; ni++)
#pragma unroll
            for (int j = 0; j < 4; j++) s[ni][j] = 0.f;

#pragma unroll
        for (int ks = 0; ks < 16; ks++) {
            const int kb = ks * 8;
#pragma unroll
            for (int ni = 0; ni < 8; ni++) {
                uint32_t bb[2];
                bb[0] = Ks[(ni * 8 + g) * KS_STR + kb + tig];
                bb[1] = Ks[(ni * 8 + g) * KS_STR + kb + tig + 4];
                mma8(s[ni], qa[ks], bb);
            }
        }

        // -------- causal mask (diagonal tile only) --------
        if (kt == qtile) {
            const int r0l = rb + g, r1l = rb + g + 8;
#pragma unroll
            for (int ni = 0; ni < 8; ni++) {
                const int c = ni * 8 + 2 * tig;
                s[ni][0] = (c     <= r0l) ? s[ni][0] : -INFINITY;
                s[ni][1] = (c + 1 <= r0l) ? s[ni][1] : -INFINITY;
                s[ni][2] = (c     <= r1l) ? s[ni][2] : -INFINITY;
                s[ni][3] = (c + 1 <= r1l) ? s[ni][3] : -INFINITY;
            }
        }

        // -------- online softmax (per row-half, quad reduce) --------
#pragma unroll
        for (int h = 0; h < 2; h++) {
            float tm = -INFINITY;
#pragma unroll
            for (int ni = 0; ni < 8; ni++)
                tm = fmaxf(tm, fmaxf(s[ni][2 * h], s[ni][2 * h + 1]));
            tm = fmaxf(tm, __shfl_xor_sync(0xffffffffu, tm, 1));
            tm = fmaxf(tm, __shfl_xor_sync(0xffffffffu, tm, 2));

            const float mn = fmaxf(mr[h], tm);
            const float alpha = __expf(mr[h] - mn);
            mr[h] = mn;

            float rs = 0.f;
#pragma unroll
            for (int ni = 0; ni < 8; ni++) {
                float p0 = __expf(s[ni][2 * h]     - mn);
                float p1 = __expf(s[ni][2 * h + 1] - mn);
                s[ni][2 * h] = p0; s[ni][2 * h + 1] = p1;
                rs += p0 + p1;
            }
            rs += __shfl_xor_sync(0xffffffffu, rs, 1);
            rs += __shfl_xor_sync(0xffffffffu, rs, 2);
            lr[h] = lr[h] * alpha + rs;

#pragma unroll
            for (int nt = 0; nt < 16; nt++) {
                o[nt][2 * h]     *= alpha;
                o[nt][2 * h + 1] *= alpha;
            }
        }
        // P -> tf32 bits (kept as float regs for shuffle)
#pragma unroll
        for (int ni = 0; ni < 8; ni++)
#pragma unroll
            for (int j = 0; j < 4; j++)
                s[ni][j] = __uint_as_float(f2tf(s[ni][j]));

        // -------- wait V(kt), all threads --------
        cp_wait<1>();
        __syncthreads();

        // -------- O += P V  (16x128 per warp); P A-frags via shuffles ----
        const uint32_t* Vu = (const uint32_t*)Vb;
        const int s1 = (lane & 0x1c) | (tig >> 1);
        const bool odd = (tig & 1);
#pragma unroll
        for (int js = 0; js < 8; js++) {
            float v00 = __shfl_sync(0xffffffffu, s[js][0], s1);
            float v01 = __shfl_sync(0xffffffffu, s[js][1], s1);
            float v10 = __shfl_sync(0xffffffffu, s[js][2], s1);
            float v11 = __shfl_sync(0xffffffffu, s[js][3], s1);
            float v20 = __shfl_sync(0xffffffffu, s[js][0], s1 + 2);
            float v21 = __shfl_sync(0xffffffffu, s[js][1], s1 + 2);
            float v30 = __shfl_sync(0xffffffffu, s[js][2], s1 + 2);
            float v31 = __shfl_sync(0xffffffffu, s[js][3], s1 + 2);
            uint32_t pa[4];
            pa[0] = __float_as_uint(odd ? v01 : v00);
            pa[1] = __float_as_uint(odd ? v11 : v10);
            pa[2] = __float_as_uint(odd ? v21 : v20);
            pa[3] = __float_as_uint(odd ? v31 : v30);
            const int jb = js * 8;
#pragma unroll
            for (int nt = 0; nt < 16; nt++) {
                uint32_t bb[2];
                bb[0] = Vu[(jb + tig)     * VS_STR + nt * 8 + g];
                bb[1] = Vu[(jb + tig + 4) * VS_STR + nt * 8 + g];
                mma8(o[nt], pa, bb);
            }
        }

        // -------- prefetch V(kt+1) after all PV reads done --------
        __syncthreads();
        issue_V(nxt);

        // -------- K(kt+1) ready for next iter --------
        cp_wait<1>();
        __syncthreads();
    }

    cp_wait<0>();

    // -------- epilogue --------
    const float inv0 = 1.0f / lr[0], inv1 = 1.0f / lr[1];
#pragma unroll
    for (int nt = 0; nt < 16; nt++) {
        const int c = nt * 8 + 2 * tig;
        *(float2*)(O + (size_t)(qbase + rb + g)     * HDIM + c) =
            make_float2(o[nt][0] * inv0, o[nt][1] * inv0);
        *(float2*)(O + (size_t)(qbase + rb + g + 8) * HDIM + c) =
            make_float2(o[nt][2] * inv1, o[nt][3] * inv1);
    }
}

// =========================== launch =============================
extern "C" void kernel_launch(void* const* d_in, const int* in_sizes, int n_in,
                              void* d_out, int out_size)
{
    (void)in_sizes; (void)n_in; (void)out_size;
    const float* X  = (const float*)d_in[0];
    const float* Wq = (const float*)d_in[1];
    const float* Wk = (const float*)d_in[2];
    const float* Wv = (const float*)d_in[3];
    float* Out = (float*)d_out;

    static int attr_set = 0;
    if (!attr_set) {
        cudaFuncSetAttribute(proj_kernel,
                             cudaFuncAttributeMaxDynamicSharedMemorySize,
                             PROJ_SMEM);
        cudaFuncSetAttribute(attn_kernel,
                             cudaFuncAttributeMaxDynamicSharedMemorySize,
                             ATT_SMEM);
        attr_set = 1;
    }

    dim3 pgrid(BSTOT / 128, 3);
    proj_kernel<<<pgrid, 256, PROJ_SMEM>>>(X, Wq, Wk, Wv);

    dim3 agrid(64, NB);   // one qtile per CTA, longest first; 2 CTAs/SM
    attn_kernel<<<agrid, 128, ATT_SMEM>>>(Out);
}

// round 6
// speedup vs baseline: 5.5891x; 1.5123x over previous
#include <cuda_runtime.h>
#include <cuda_fp16.h>
#include <math.h>
#include <stdint.h>

// Problem shape (fixed by the dataset)
#define NB      4
#define SEQ     4096
#define DDIM    1024
#define HDIM    128
#define BSTOT   (NB * SEQ)          // 16384 rows

// ---------------- scratch (no cudaMalloc allowed) ----------------
// fp16 Q (pre-scaled by 1/sqrt(128)) / K / V
__device__ __half g_Qh[BSTOT * HDIM];
__device__ __half g_Kh[BSTOT * HDIM];
__device__ __half g_Vh[BSTOT * HDIM];

// ------------------- helpers -------------------
__device__ __forceinline__ uint32_t f2tf(float f) {
    uint32_t u; asm("cvt.rna.tf32.f32 %0, %1;" : "=r"(u) : "f"(f)); return u;
}
// tf32: D += A(16x8, row) * B(8x8, col), fp32 accum  (projection kernel)
__device__ __forceinline__ void mma8(float* c, const uint32_t* a, const uint32_t* b) {
    asm volatile("mma.sync.aligned.m16n8k8.row.col.f32.tf32.tf32.f32 "
        "{%0,%1,%2,%3}, {%4,%5,%6,%7}, {%8,%9}, {%0,%1,%2,%3};"
        : "+f"(c[0]), "+f"(c[1]), "+f"(c[2]), "+f"(c[3])
        : "r"(a[0]), "r"(a[1]), "r"(a[2]), "r"(a[3]), "r"(b[0]), "r"(b[1]));
}
// fp16: D += A(16x16, row) * B(16x8, col), fp32 accum  (attention kernel)
__device__ __forceinline__ void mma16(float* c, const uint32_t* a, const uint32_t* b) {
    asm volatile("mma.sync.aligned.m16n8k16.row.col.f32.f16.f16.f32 "
        "{%0,%1,%2,%3}, {%4,%5,%6,%7}, {%8,%9}, {%0,%1,%2,%3};"
        : "+f"(c[0]), "+f"(c[1]), "+f"(c[2]), "+f"(c[3])
        : "r"(a[0]), "r"(a[1]), "r"(a[2]), "r"(a[3]), "r"(b[0]), "r"(b[1]));
}
__device__ __forceinline__ void ldsm4(uint32_t& r0, uint32_t& r1, uint32_t& r2, uint32_t& r3,
                                      uint32_t addr) {
    asm volatile("ldmatrix.sync.aligned.m8n8.x4.shared.b16 {%0,%1,%2,%3}, [%4];"
        : "=r"(r0), "=r"(r1), "=r"(r2), "=r"(r3) : "r"(addr));
}
__device__ __forceinline__ void ldsm4t(uint32_t& r0, uint32_t& r1, uint32_t& r2, uint32_t& r3,
                                       uint32_t addr) {
    asm volatile("ldmatrix.sync.aligned.m8n8.x4.trans.shared.b16 {%0,%1,%2,%3}, [%4];"
        : "=r"(r0), "=r"(r1), "=r"(r2), "=r"(r3) : "r"(addr));
}
// pack two f32 -> f16x2 (lo = first element)
__device__ __forceinline__ uint32_t ph2(float lo, float hi) {
    uint32_t r; asm("cvt.rn.f16x2.f32 %0, %1, %2;" : "=r"(r) : "f"(hi), "f"(lo)); return r;
}

__device__ __forceinline__ uint32_t smaddr(const void* p) {
    return (uint32_t)__cvta_generic_to_shared(p);
}
__device__ __forceinline__ void cp16(uint32_t s, const void* g) {
    asm volatile("cp.async.ca.shared.global [%0], [%1], 16;" :: "r"(s), "l"(g));
}
__device__ __forceinline__ void cp_commit() {
    asm volatile("cp.async.commit_group;");
}
template <int N>
__device__ __forceinline__ void cp_wait() {
    asm volatile("cp.async.wait_group %0;" :: "n"(N));
}

// ======================= QKV projection =========================
// Out[16384,128] = X[16384,1024] @ W[1024,128]; tf32 mma, 2-stage cp.async.
// Epilogue writes fp16 (Q additionally pre-scaled by 1/sqrt(128)).
#define XS_STR 36
#define WS_STR 136
#define PROJ_SMEM ((2 * 128 * XS_STR + 2 * 32 * WS_STR) * 4)   // 71680 B

__global__ __launch_bounds__(256, 2) void proj_kernel(
    const float* __restrict__ X,
    const float* __restrict__ Wq,
    const float* __restrict__ Wk,
    const float* __restrict__ Wv)
{
    const float* W    = (blockIdx.y == 0) ? Wq : ((blockIdx.y == 1) ? Wk : Wv);
    __half*      Outh = (blockIdx.y == 0) ? g_Qh : ((blockIdx.y == 1) ? g_Kh : g_Vh);

    extern __shared__ float psm[];
    float* Xb = psm;                        // [2][128*36]
    float* Wb = psm + 2 * 128 * XS_STR;     // [2][32*136]

    const int tid  = threadIdx.x;
    const int warp = tid >> 5, lane = tid & 31;
    const int g = lane >> 2, tig = lane & 3;
    const int wm = warp & 3;      // 4 warps along M (32 rows each)
    const int wn = warp >> 2;     // 2 warps along N (64 cols each)
    const int row0 = blockIdx.x * 128;

    auto issue_stage = [&](int k0, int s) {
        float* Xd = Xb + s * 128 * XS_STR;
        float* Wd = Wb + s * 32 * WS_STR;
#pragma unroll
        for (int c = tid; c < 1024; c += 256) {
            int r = c >> 3, c4 = c & 7;
            cp16(smaddr(Xd + r * XS_STR + c4 * 4),
                 X + (size_t)(row0 + r) * DDIM + k0 + c4 * 4);
        }
#pragma unroll
        for (int c = tid; c < 1024; c += 256) {
            int r = c >> 5, c4 = c & 31;
            cp16(smaddr(Wd + r * WS_STR + c4 * 4),
                 W + (size_t)(k0 + r) * HDIM + c4 * 4);
        }
        cp_commit();
    };

    float acc[2][8][4];
#pragma unroll
    for (int mi = 0; mi < 2; mi++)
#pragma unroll
        for (int ni = 0; ni < 8; ni++)
#pragma unroll
            for (int j = 0; j < 4; j++) acc[mi][ni][j] = 0.f;

    issue_stage(0, 0);

    for (int ki = 0; ki < 32; ki++) {
        if (ki < 31) { issue_stage((ki + 1) * 32, (ki + 1) & 1); cp_wait<1>(); }
        else         { cp_wait<0>(); }
        __syncthreads();

        const float* Xs = Xb + (ki & 1) * 128 * XS_STR;
        const float* Ws = Wb + (ki & 1) * 32 * WS_STR;
#pragma unroll
        for (int ks = 0; ks < 4; ks++) {
            const int kb = ks * 8;
            uint32_t a[2][4];
#pragma unroll
            for (int mi = 0; mi < 2; mi++) {
                const int rbm = wm * 32 + mi * 16;
                a[mi][0] = f2tf(Xs[(rbm + g)     * XS_STR + kb + tig]);
                a[mi][1] = f2tf(Xs[(rbm + g + 8) * XS_STR + kb + tig]);
                a[mi][2] = f2tf(Xs[(rbm + g)     * XS_STR + kb + tig + 4]);
                a[mi][3] = f2tf(Xs[(rbm + g + 8) * XS_STR + kb + tig + 4]);
            }
#pragma unroll
            for (int ni = 0; ni < 8; ni++) {
                uint32_t bb[2];
                const int col = wn * 64 + ni * 8 + g;
                bb[0] = f2tf(Ws[(kb + tig)     * WS_STR + col]);
                bb[1] = f2tf(Ws[(kb + tig + 4) * WS_STR + col]);
                mma8(acc[0][ni], a[0], bb);
                mma8(acc[1][ni], a[1], bb);
            }
        }
        __syncthreads();
    }

    // epilogue: fp16 (Q pre-scaled)
    const float osc = (blockIdx.y == 0) ? 0.088388347648318447f : 1.0f;
#pragma unroll
    for (int mi = 0; mi < 2; mi++) {
        const int r = row0 + wm * 32 + mi * 16 + g;
#pragma unroll
        for (int ni = 0; ni < 8; ni++) {
            const int c = wn * 64 + ni * 8 + 2 * tig;
            *(uint32_t*)(Outh + (size_t)r       * HDIM + c) =
                ph2(acc[mi][ni][0] * osc, acc[mi][ni][1] * osc);
            *(uint32_t*)(Outh + (size_t)(r + 8) * HDIM + c) =
                ph2(acc[mi][ni][2] * osc, acc[mi][ni][3] * osc);
        }
    }
}

// ======================= flash attention ========================
// 128 threads = 4 warps; BM=BN=64; warp w owns rows w*16..w*16+15.
// fp16 m16n8k16 MMAs, ldmatrix fragment loads; one qtile/CTA, longest first.
#define HS 136                       // half-stride per K/V smem row (272 B)
#define ATT_SMEM (3 * 64 * HS * 2)   // 2 K bufs + 1 V buf = 52224 B

__global__ __launch_bounds__(128) void attn_kernel(float* __restrict__ Out)
{
    extern __shared__ __half hsm[];
    __half* Kb = hsm;                  // [2][64*HS]
    __half* Vb = hsm + 2 * 64 * HS;    // [64*HS]

    const int tid  = threadIdx.x;
    const int warp = tid >> 5, lane = tid & 31;
    const int g = lane >> 2, tig = lane & 3;
    const int rb = warp * 16;
    const int b  = blockIdx.y;

    const __half* Q = g_Qh + (size_t)b * SEQ * HDIM;
    const __half* K = g_Kh + (size_t)b * SEQ * HDIM;
    const __half* V = g_Vh + (size_t)b * SEQ * HDIM;
    float*        O = Out  + (size_t)b * SEQ * HDIM;

    const int qtile = 63 - (int)blockIdx.x;   // longest job first
    const int qbase = qtile * 64;

    auto issue_K = [&](int kbase, int s) {
        __half* Kd = Kb + s * 64 * HS;
#pragma unroll
        for (int c = tid; c < 1024; c += 128) {
            int r = c >> 4, c8 = c & 15;
            cp16(smaddr(Kd + r * HS + c8 * 8),
                 K + (size_t)(kbase + r) * HDIM + c8 * 8);
        }
        cp_commit();
    };
    auto issue_V = [&](int kbase) {
#pragma unroll
        for (int c = tid; c < 1024; c += 128) {
            int r = c >> 4, c8 = c & 15;
            cp16(smaddr(Vb + r * HS + c8 * 8),
                 V + (size_t)(kbase + r) * HDIM + c8 * 8);
        }
        cp_commit();
    };

    // Q -> register A-fragments (fp16, pre-scaled in gmem)
    uint32_t qa[8][4];
#pragma unroll
    for (int ks = 0; ks < 8; ks++) {
        const __half* q0 = Q + (size_t)(qbase + rb + g)     * HDIM + ks * 16;
        const __half* q1 = Q + (size_t)(qbase + rb + g + 8) * HDIM + ks * 16;
        qa[ks][0] = *(const uint32_t*)(q0 + 2 * tig);
        qa[ks][1] = *(const uint32_t*)(q1 + 2 * tig);
        qa[ks][2] = *(const uint32_t*)(q0 + 2 * tig + 8);
        qa[ks][3] = *(const uint32_t*)(q1 + 2 * tig + 8);
    }

    float o[16][4];
#pragma unroll
    for (int nt = 0; nt < 16; nt++)
#pragma unroll
        for (int j = 0; j < 4; j++) o[nt][j] = 0.f;
    float mr[2] = {-INFINITY, -INFINITY};
    float lr[2] = {0.f, 0.f};

    // ldmatrix per-thread offsets (in halves)
    const int kq_off = (lane & 7) * HS + (lane >> 3) * 8;   // K: row n, k-block
    const int vv_off = lane * HS;                            // V: row k (seq)

    // prologue
    issue_K(0, 0);
    issue_V(0);
    cp_wait<1>();        // K(0) ready
    __syncthreads();

    for (int kt = 0; kt <= qtile; kt++) {
        const int nxt = (kt + 1 <= qtile) ? (kt + 1) * 64 : qtile * 64;
        issue_K(nxt, (kt + 1) & 1);           // overlaps with QK below

        const uint32_t KsA = smaddr(Kb + (kt & 1) * 64 * HS);

        // -------- S = Q K^T  (16x64 per warp) --------
        float s[8][4];
#pragma unroll
        for (int ni = 0; ni < 8; ni++)
#pragma unroll
            for (int j = 0; j < 4; j++) s[ni][j] = 0.f;

#pragma unroll
        for (int ni = 0; ni < 8; ni++) {
            const uint32_t base = KsA + (uint32_t)(ni * 8 * HS + kq_off) * 2;
#pragma unroll
            for (int kc = 0; kc < 4; kc++) {
                uint32_t r0, r1, r2, r3;
                ldsm4(r0, r1, r2, r3, base + kc * 64);   // 32 halves = 64 B
                uint32_t b01[2] = {r0, r1}, b23[2] = {r2, r3};
                mma16(s[ni], qa[2 * kc],     b01);
                mma16(s[ni], qa[2 * kc + 1], b23);
            }
        }

        // -------- causal mask (diagonal tile only) --------
        if (kt == qtile) {
            const int r0l = rb + g, r1l = rb + g + 8;
#pragma unroll
            for (int ni = 0; ni < 8; ni++) {
                const int c = ni * 8 + 2 * tig;
                s[ni][0] = (c     <= r0l) ? s[ni][0] : -INFINITY;
                s[ni][1] = (c + 1 <= r0l) ? s[ni][1] : -INFINITY;
                s[ni][2] = (c     <= r1l) ? s[ni][2] : -INFINITY;
                s[ni][3] = (c + 1 <= r1l) ? s[ni][3] : -INFINITY;
            }
        }

        // -------- online softmax (per row-half, quad reduce) --------
#pragma unroll
        for (int h = 0; h < 2; h++) {
            float tm = -INFINITY;
#pragma unroll
            for (int ni = 0; ni < 8; ni++)
                tm = fmaxf(tm, fmaxf(s[ni][2 * h], s[ni][2 * h + 1]));
            tm = fmaxf(tm, __shfl_xor_sync(0xffffffffu, tm, 1));
            tm = fmaxf(tm, __shfl_xor_sync(0xffffffffu, tm, 2));

            const float mn = fmaxf(mr[h], tm);
            const float alpha = __expf(mr[h] - mn);
            mr[h] = mn;

            float rs = 0.f;
#pragma unroll
            for (int ni = 0; ni < 8; ni++) {
                float p0 = __expf(s[ni][2 * h]     - mn);
                float p1 = __expf(s[ni][2 * h + 1] - mn);
                s[ni][2 * h] = p0; s[ni][2 * h + 1] = p1;
                rs += p0 + p1;
            }
            rs += __shfl_xor_sync(0xffffffffu, rs, 1);
            rs += __shfl_xor_sync(0xffffffffu, rs, 2);
            lr[h] = lr[h] * alpha + rs;

#pragma unroll
            for (int nt = 0; nt < 16; nt++) {
                o[nt][2 * h]     *= alpha;
                o[nt][2 * h + 1] *= alpha;
            }
        }

        // -------- P -> fp16 A-fragments (C-frag pairs ARE A-frag pairs) ----
        uint32_t pa[4][4];
#pragma unroll
        for (int js = 0; js < 4; js++) {
            pa[js][0] = ph2(s[2 * js][0],     s[2 * js][1]);
            pa[js][1] = ph2(s[2 * js][2],     s[2 * js][3]);
            pa[js][2] = ph2(s[2 * js + 1][0], s[2 * js + 1][1]);
            pa[js][3] = ph2(s[2 * js + 1][2], s[2 * js + 1][3]);
        }

        // -------- wait V(kt), all threads --------
        cp_wait<1>();
        __syncthreads();

        // -------- O += P V  (16x128 per warp) --------
        const uint32_t VsA = smaddr(Vb);
#pragma unroll
        for (int nt = 0; nt < 16; nt++) {
            const uint32_t base = VsA + (uint32_t)(vv_off + nt * 8) * 2;
#pragma unroll
            for (int kc = 0; kc < 2; kc++) {
                uint32_t r0, r1, r2, r3;
                ldsm4t(r0, r1, r2, r3, base + kc * (32 * HS * 2));
                uint32_t b01[2] = {r0, r1}, b23[2] = {r2, r3};
                mma16(o[nt], pa[2 * kc],     b01);
                mma16(o[nt], pa[2 * kc + 1], b23);
            }
        }

        // -------- prefetch V(kt+1) after all PV reads done --------
        __syncthreads();
        issue_V(nxt);

        // -------- K(kt+1) ready for next iter --------
        cp_wait<1>();
        __syncthreads();
    }

    cp_wait<0>();

    // -------- epilogue --------
    const float inv0 = 1.0f / lr[0], inv1 = 1.0f / lr[1];
#pragma unroll
    for (int nt = 0; nt < 16; nt++) {
        const int c = nt * 8 + 2 * tig;
        *(float2*)(O + (size_t)(qbase + rb + g)     * HDIM + c) =
            make_float2(o[nt][0] * inv0, o[nt][1] * inv0);
        *(float2*)(O + (size_t)(qbase + rb + g + 8) * HDIM + c) =
            make_float2(o[nt][2] * inv1, o[nt][3] * inv1);
    }
}

// =========================== launch =============================
extern "C" void kernel_launch(void* const* d_in, const int* in_sizes, int n_in,
                              void* d_out, int out_size)
{
    (void)in_sizes; (void)n_in; (void)out_size;
    const float* X  = (const float*)d_in[0];
    const float* Wq = (const float*)d_in[1];
    const float* Wk = (const float*)d_in[2];
    const float* Wv = (const float*)d_in[3];
    float* Out = (float*)d_out;

    static int attr_set = 0;
    if (!attr_set) {
        cudaFuncSetAttribute(proj_kernel,
                             cudaFuncAttributeMaxDynamicSharedMemorySize,
                             PROJ_SMEM);
        cudaFuncSetAttribute(attn_kernel,
                             cudaFuncAttributeMaxDynamicSharedMemorySize,
                             ATT_SMEM);
        attr_set = 1;
    }

    dim3 pgrid(BSTOT / 128, 3);
    proj_kernel<<<pgrid, 256, PROJ_SMEM>>>(X, Wq, Wk, Wv);

    dim3 agrid(64, NB);   // one qtile per CTA, longest first
    attn_kernel<<<agrid, 128, ATT_SMEM>>>(Out);
}

// round 7
// speedup vs baseline: 6.3142x; 1.1297x over previous
#include <cuda_runtime.h>
#include <cuda_fp16.h>
#include <math.h>
#include <stdint.h>

// Problem shape (fixed by the dataset)
#define NB      4
#define SEQ     4096
#define DDIM    1024
#define HDIM    128
#define BSTOT   (NB * SEQ)          // 16384 rows

// ---------------- scratch (no cudaMalloc allowed) ----------------
__device__ __half g_Xh[BSTOT * DDIM];       // fp16 X
__device__ __half g_Wh[3 * DDIM * HDIM];    // fp16 Wq|Wk|Wv
__device__ __half g_Qh[BSTOT * HDIM];       // fp16 Q (pre-scaled by 1/sqrt(128))
__device__ __half g_Kh[BSTOT * HDIM];
__device__ __half g_Vh[BSTOT * HDIM];

// ------------------- helpers -------------------
// fp16: D += A(16x16, row) * B(16x8, col), fp32 accum
__device__ __forceinline__ void mma16(float* c, const uint32_t* a, const uint32_t* b) {
    asm volatile("mma.sync.aligned.m16n8k16.row.col.f32.f16.f16.f32 "
        "{%0,%1,%2,%3}, {%4,%5,%6,%7}, {%8,%9}, {%0,%1,%2,%3};"
        : "+f"(c[0]), "+f"(c[1]), "+f"(c[2]), "+f"(c[3])
        : "r"(a[0]), "r"(a[1]), "r"(a[2]), "r"(a[3]), "r"(b[0]), "r"(b[1]));
}
__device__ __forceinline__ void ldsm4(uint32_t& r0, uint32_t& r1, uint32_t& r2, uint32_t& r3,
                                      uint32_t addr) {
    asm volatile("ldmatrix.sync.aligned.m8n8.x4.shared.b16 {%0,%1,%2,%3}, [%4];"
        : "=r"(r0), "=r"(r1), "=r"(r2), "=r"(r3) : "r"(addr));
}
__device__ __forceinline__ void ldsm4t(uint32_t& r0, uint32_t& r1, uint32_t& r2, uint32_t& r3,
                                       uint32_t addr) {
    asm volatile("ldmatrix.sync.aligned.m8n8.x4.trans.shared.b16 {%0,%1,%2,%3}, [%4];"
        : "=r"(r0), "=r"(r1), "=r"(r2), "=r"(r3) : "r"(addr));
}
// pack two f32 -> f16x2 (lo = first element)
__device__ __forceinline__ uint32_t ph2(float lo, float hi) {
    uint32_t r; asm("cvt.rn.f16x2.f32 %0, %1, %2;" : "=r"(r) : "f"(hi), "f"(lo)); return r;
}
__device__ __forceinline__ uint32_t smaddr(const void* p) {
    return (uint32_t)__cvta_generic_to_shared(p);
}
__device__ __forceinline__ void cp16(uint32_t s, const void* g) {
    asm volatile("cp.async.ca.shared.global [%0], [%1], 16;" :: "r"(s), "l"(g));
}
__device__ __forceinline__ void cp_commit() {
    asm volatile("cp.async.commit_group;");
}
template <int N>
__device__ __forceinline__ void cp_wait() {
    asm volatile("cp.async.wait_group %0;" :: "n"(N));
}

// ======================= fp32 -> fp16 converts =========================
__global__ __launch_bounds__(256) void convert_X_kernel(const float* __restrict__ X)
{
    // 8 floats per thread
    size_t i = ((size_t)blockIdx.x * 256 + threadIdx.x) * 8;
    float4 a = *(const float4*)(X + i);
    float4 b = *(const float4*)(X + i + 4);
    uint4 o;
    o.x = ph2(a.x, a.y); o.y = ph2(a.z, a.w);
    o.z = ph2(b.x, b.y); o.w = ph2(b.z, b.w);
    *(uint4*)(g_Xh + i) = o;
}
__global__ __launch_bounds__(256) void convert_W_kernel(
    const float* __restrict__ Wq, const float* __restrict__ Wk,
    const float* __restrict__ Wv)
{
    const float* W = (blockIdx.y == 0) ? Wq : ((blockIdx.y == 1) ? Wk : Wv);
    size_t i = ((size_t)blockIdx.x * 256 + threadIdx.x) * 8;   // 64 blocks cover 131072 floats
    float4 a = *(const float4*)(W + i);
    float4 b = *(const float4*)(W + i + 4);
    uint4 o;
    o.x = ph2(a.x, a.y); o.y = ph2(a.z, a.w);
    o.z = ph2(b.x, b.y); o.w = ph2(b.z, b.w);
    *(uint4*)(g_Wh + (size_t)blockIdx.y * DDIM * HDIM + i) = o;
}

// ======================= QKV projection (fp16) =========================
// Out[16384,128] = Xh[16384,1024] @ Wh[1024,128]; m16n8k16, 2-stage cp.async.
#define PXS 40    // X tile stride in halves (80 B rows; ldsm phase conflict-free)
#define PWS 136   // W tile stride in halves (272 B rows)
#define PROJ_SMEM ((2 * 128 * PXS + 2 * 32 * PWS) * 2)   // 37888 B

__global__ __launch_bounds__(256, 2) void proj_kernel()
{
    const int mat = blockIdx.y;
    const __half* Xg = g_Xh;
    const __half* Wg = g_Wh + (size_t)mat * DDIM * HDIM;
    __half*      Outh = (mat == 0) ? g_Qh : ((mat == 1) ? g_Kh : g_Vh);

    extern __shared__ __half psm[];
    __half* Xb = psm;                      // [2][128*PXS]
    __half* Wb = psm + 2 * 128 * PXS;      // [2][32*PWS]

    const int tid  = threadIdx.x;
    const int warp = tid >> 5, lane = tid & 31;
    const int g = lane >> 2, tig = lane & 3;
    const int wm = warp & 3;      // 4 warps along M (32 rows each)
    const int wn = warp >> 2;     // 2 warps along N (64 cols each)
    const int row0 = blockIdx.x * 128;

    auto issue_stage = [&](int k0, int s) {
        __half* Xd = Xb + s * 128 * PXS;
        __half* Wd = Wb + s * 32 * PWS;
#pragma unroll
        for (int c = tid; c < 512; c += 256) {       // X: 128 rows x 4 chunks
            int r = c >> 2, c8 = c & 3;
            cp16(smaddr(Xd + r * PXS + c8 * 8),
                 Xg + (size_t)(row0 + r) * DDIM + k0 + c8 * 8);
        }
#pragma unroll
        for (int c = tid; c < 512; c += 256) {       // W: 32 rows x 16 chunks
            int r = c >> 4, c8 = c & 15;
            cp16(smaddr(Wd + r * PWS + c8 * 8),
                 Wg + (size_t)(k0 + r) * HDIM + c8 * 8);
        }
        cp_commit();
    };

    float acc[2][8][4];
#pragma unroll
    for (int mi = 0; mi < 2; mi++)
#pragma unroll
        for (int ni = 0; ni < 8; ni++)
#pragma unroll
            for (int j = 0; j < 4; j++) acc[mi][ni][j] = 0.f;

    issue_stage(0, 0);

    // ldmatrix thread offsets
    const int a_off = (lane & 15) * PXS + (lane >> 4) * 8;   // A m16k16 pattern
    const int b_off = lane * PWS;                            // B (trans) k-rows

    for (int ki = 0; ki < 32; ki++) {
        if (ki < 31) { issue_stage((ki + 1) * 32, (ki + 1) & 1); cp_wait<1>(); }
        else         { cp_wait<0>(); }
        __syncthreads();

        const uint32_t XsA = smaddr(Xb + (ki & 1) * 128 * PXS);
        const uint32_t WsA = smaddr(Wb + (ki & 1) * 32 * PWS);

        // A fragments: 2 m-blocks x 2 k16-chunks
        uint32_t a[2][2][4];
#pragma unroll
        for (int mi = 0; mi < 2; mi++)
#pragma unroll
            for (int kc = 0; kc < 2; kc++) {
                uint32_t addr = XsA + (uint32_t)((wm * 32 + mi * 16) * PXS + kc * 16 + a_off) * 2;
                ldsm4(a[mi][kc][0], a[mi][kc][1], a[mi][kc][2], a[mi][kc][3], addr);
            }
#pragma unroll
        for (int ni = 0; ni < 8; ni++) {
            uint32_t r0, r1, r2, r3;
            uint32_t addr = WsA + (uint32_t)(b_off + wn * 64 + ni * 8) * 2;
            ldsm4t(r0, r1, r2, r3, addr);        // k0-15 -> {r0,r1}, k16-31 -> {r2,r3}
            uint32_t b01[2] = {r0, r1}, b23[2] = {r2, r3};
#pragma unroll
            for (int mi = 0; mi < 2; mi++) {
                mma16(acc[mi][ni], a[mi][0], b01);
                mma16(acc[mi][ni], a[mi][1], b23);
            }
        }
        __syncthreads();
    }

    // epilogue: fp16 (Q pre-scaled)
    const float osc = (mat == 0) ? 0.088388347648318447f : 1.0f;
#pragma unroll
    for (int mi = 0; mi < 2; mi++) {
        const int r = row0 + wm * 32 + mi * 16 + g;
#pragma unroll
        for (int ni = 0; ni < 8; ni++) {
            const int c = wn * 64 + ni * 8 + 2 * tig;
            *(uint32_t*)(Outh + (size_t)r       * HDIM + c) =
                ph2(acc[mi][ni][0] * osc, acc[mi][ni][1] * osc);
            *(uint32_t*)(Outh + (size_t)(r + 8) * HDIM + c) =
                ph2(acc[mi][ni][2] * osc, acc[mi][ni][3] * osc);
        }
    }
}

// ======================= flash attention ========================
// 128 threads = 4 warps; BM=BN=64; warp w owns rows w*16..w*16+15.
// fp16 m16n8k16 MMAs; K+V double-buffered single-group stages, 2-deep prefetch.
#define HS 136                       // half-stride per K/V smem row (272 B)
#define ATT_SMEM (4 * 64 * HS * 2)   // 2 K bufs + 2 V bufs = 69632 B

__global__ __launch_bounds__(128) void attn_kernel(float* __restrict__ Out)
{
    extern __shared__ __half hsm[];
    __half* Kb = hsm;                  // [2][64*HS]
    __half* Vb = hsm + 2 * 64 * HS;    // [2][64*HS]

    const int tid  = threadIdx.x;
    const int warp = tid >> 5, lane = tid & 31;
    const int g = lane >> 2, tig = lane & 3;
    const int rb = warp * 16;
    const int b  = blockIdx.y;

    const __half* Q = g_Qh + (size_t)b * SEQ * HDIM;
    const __half* K = g_Kh + (size_t)b * SEQ * HDIM;
    const __half* V = g_Vh + (size_t)b * SEQ * HDIM;
    float*        O = Out  + (size_t)b * SEQ * HDIM;

    const int qtile = 63 - (int)blockIdx.x;   // longest job first
    const int qbase = qtile * 64;

    auto issue_stage = [&](int kbase, int s) {
        __half* Kd = Kb + s * 64 * HS;
        __half* Vd = Vb + s * 64 * HS;
#pragma unroll
        for (int c = tid; c < 1024; c += 128) {
            int r = c >> 4, c8 = c & 15;
            cp16(smaddr(Kd + r * HS + c8 * 8),
                 K + (size_t)(kbase + r) * HDIM + c8 * 8);
            cp16(smaddr(Vd + r * HS + c8 * 8),
                 V + (size_t)(kbase + r) * HDIM + c8 * 8);
        }
        cp_commit();
    };

    // Q -> register A-fragments (fp16, pre-scaled in gmem)
    uint32_t qa[8][4];
#pragma unroll
    for (int ks = 0; ks < 8; ks++) {
        const __half* q0 = Q + (size_t)(qbase + rb + g)     * HDIM + ks * 16;
        const __half* q1 = Q + (size_t)(qbase + rb + g + 8) * HDIM + ks * 16;
        qa[ks][0] = *(const uint32_t*)(q0 + 2 * tig);
        qa[ks][1] = *(const uint32_t*)(q1 + 2 * tig);
        qa[ks][2] = *(const uint32_t*)(q0 + 2 * tig + 8);
        qa[ks][3] = *(const uint32_t*)(q1 + 2 * tig + 8);
    }

    float o[16][4];
#pragma unroll
    for (int nt = 0; nt < 16; nt++)
#pragma unroll
        for (int j = 0; j < 4; j++) o[nt][j] = 0.f;
    float mr[2] = {-INFINITY, -INFINITY};
    float lr[2] = {0.f, 0.f};

    // ldmatrix per-thread offsets (in halves)
    const int kq_off = (lane & 7) * HS + (lane >> 3) * 8;   // K: row n, k-block
    const int vv_off = lane * HS;                            // V: row k (seq)

    // prologue: 2-deep prefetch
    issue_stage(0, 0);
    if (qtile >= 1) issue_stage(64, 1); else cp_commit();

    for (int kt = 0; kt <= qtile; kt++) {
        cp_wait<1>();          // stage kt arrived (stage kt+1 may be pending)
        __syncthreads();

        const uint32_t KsA = smaddr(Kb + (kt & 1) * 64 * HS);
        const uint32_t VsA = smaddr(Vb + (kt & 1) * 64 * HS);

        // -------- S = Q K^T  (16x64 per warp) --------
        float s[8][4];
#pragma unroll
        for (int ni = 0; ni < 8; ni++)
#pragma unroll
            for (int j = 0; j < 4; j++) s[ni][j] = 0.f;

#pragma unroll
        for (int ni = 0; ni < 8; ni++) {
            const uint32_t base = KsA + (uint32_t)(ni * 8 * HS + kq_off) * 2;
#pragma unroll
            for (int kc = 0; kc < 4; kc++) {
                uint32_t r0, r1, r2, r3;
                ldsm4(r0, r1, r2, r3, base + kc * 64);   // 32 halves = 64 B
                uint32_t b01[2] = {r0, r1}, b23[2] = {r2, r3};
                mma16(s[ni], qa[2 * kc],     b01);
                mma16(s[ni], qa[2 * kc + 1], b23);
            }
        }

        // -------- causal mask (diagonal tile only) --------
        if (kt == qtile) {
            const int r0l = rb + g, r1l = rb + g + 8;
#pragma unroll
            for (int ni = 0; ni < 8; ni++) {
                const int c = ni * 8 + 2 * tig;
                s[ni][0] = (c     <= r0l) ? s[ni][0] : -INFINITY;
                s[ni][1] = (c + 1 <= r0l) ? s[ni][1] : -INFINITY;
                s[ni][2] = (c     <= r1l) ? s[ni][2] : -INFINITY;
                s[ni][3] = (c + 1 <= r1l) ? s[ni][3] : -INFINITY;
            }
        }

        // -------- online softmax (per row-half, quad reduce) --------
#pragma unroll
        for (int h = 0; h < 2; h++) {
            float tm = -INFINITY;
#pragma unroll
            for (int ni = 0; ni < 8; ni++)
                tm = fmaxf(tm, fmaxf(s[ni][2 * h], s[ni][2 * h + 1]));
            tm = fmaxf(tm, __shfl_xor_sync(0xffffffffu, tm, 1));
            tm = fmaxf(tm, __shfl_xor_sync(0xffffffffu, tm, 2));

            const float mn = fmaxf(mr[h], tm);
            const float alpha = __expf(mr[h] - mn);
            mr[h] = mn;

            float rs = 0.f;
#pragma unroll
            for (int ni = 0; ni < 8; ni++) {
                float p0 = __expf(s[ni][2 * h]     - mn);
                float p1 = __expf(s[ni][2 * h + 1] - mn);
                s[ni][2 * h] = p0; s[ni][2 * h + 1] = p1;
                rs += p0 + p1;
            }
            rs += __shfl_xor_sync(0xffffffffu, rs, 1);
            rs += __shfl_xor_sync(0xffffffffu, rs, 2);
            lr[h] = lr[h] * alpha + rs;

#pragma unroll
            for (int nt = 0; nt < 16; nt++) {
                o[nt][2 * h]     *= alpha;
                o[nt][2 * h + 1] *= alpha;
            }
        }

        // -------- P -> fp16 A-fragments (C-frag pairs ARE A-frag pairs) ----
        uint32_t pa[4][4];
#pragma unroll
        for (int js = 0; js < 4; js++) {
            pa[js][0] = ph2(s[2 * js][0],     s[2 * js][1]);
            pa[js][1] = ph2(s[2 * js][2],     s[2 * js][3]);
            pa[js][2] = ph2(s[2 * js + 1][0], s[2 * js + 1][1]);
            pa[js][3] = ph2(s[2 * js + 1][2], s[2 * js + 1][3]);
        }

        // -------- O += P V  (16x128 per warp) --------
#pragma unroll
        for (int nt = 0; nt < 16; nt++) {
            const uint32_t base = VsA + (uint32_t)(vv_off + nt * 8) * 2;
#pragma unroll
            for (int kc = 0; kc < 2; kc++) {
                uint32_t r0, r1, r2, r3;
                ldsm4t(r0, r1, r2, r3, base + kc * (32 * HS * 2));
                uint32_t b01[2] = {r0, r1}, b23[2] = {r2, r3};
                mma16(o[nt], pa[2 * kc],     b01);
                mma16(o[nt], pa[2 * kc + 1], b23);
            }
        }

        // -------- all warps done reading stage kt; refill its buffer --------
        __syncthreads();
        if (kt + 2 <= qtile) issue_stage((kt + 2) * 64, kt & 1);
        else                 cp_commit();    // keep wait<1> invariant exact
    }

    cp_wait<0>();

    // -------- epilogue --------
    const float inv0 = 1.0f / lr[0], inv1 = 1.0f / lr[1];
#pragma unroll
    for (int nt = 0; nt < 16; nt++) {
        const int c = nt * 8 + 2 * tig;
        *(float2*)(O + (size_t)(qbase + rb + g)     * HDIM + c) =
            make_float2(o[nt][0] * inv0, o[nt][1] * inv0);
        *(float2*)(O + (size_t)(qbase + rb + g + 8) * HDIM + c) =
            make_float2(o[nt][2] * inv1, o[nt][3] * inv1);
    }
}

// =========================== launch =============================
extern "C" void kernel_launch(void* const* d_in, const int* in_sizes, int n_in,
                              void* d_out, int out_size)
{
    (void)in_sizes; (void)n_in; (void)out_size;
    const float* X  = (const float*)d_in[0];
    const float* Wq = (const float*)d_in[1];
    const float* Wk = (const float*)d_in[2];
    const float* Wv = (const float*)d_in[3];
    float* Out = (float*)d_out;

    static int attr_set = 0;
    if (!attr_set) {
        cudaFuncSetAttribute(proj_kernel,
                             cudaFuncAttributeMaxDynamicSharedMemorySize,
                             PROJ_SMEM);
        cudaFuncSetAttribute(attn_kernel,
                             cudaFuncAttributeMaxDynamicSharedMemorySize,
                             ATT_SMEM);
        attr_set = 1;
    }

    // fp32 -> fp16 converts
    convert_X_kernel<<<BSTOT * DDIM / (256 * 8), 256>>>(X);
    dim3 wgrid(DDIM * HDIM / (256 * 8), 3);
    convert_W_kernel<<<wgrid, 256>>>(Wq, Wk, Wv);

    // QKV projections (fp16 tensor cores)
    dim3 pgrid(BSTOT / 128, 3);
    proj_kernel<<<pgrid, 256, PROJ_SMEM>>>();

    // Flash attention
    dim3 agrid(64, NB);   // one qtile per CTA, longest first
    attn_kernel<<<agrid, 128, ATT_SMEM>>>(Out);
}

// round 8
// speedup vs baseline: 6.9116x; 1.0946x over previous
#include <cuda_runtime.h>
#include <cuda_fp16.h>
#include <math.h>
#include <stdint.h>

// Problem shape (fixed by the dataset)
#define NB      4
#define SEQ     4096
#define DDIM    1024
#define HDIM    128
#define BSTOT   (NB * SEQ)          // 16384 rows
#define NQT     64                  // q-tiles per batch (SEQ/64)

// ---------------- scratch (no cudaMalloc allowed) ----------------
__device__ __half g_Xh[BSTOT * DDIM];       // fp16 X
__device__ __half g_Wh[3 * DDIM * HDIM];    // fp16 Wq|Wk|Wv
__device__ __half g_Qh[BSTOT * HDIM];       // fp16 Q (pre-scaled by 1/sqrt(128))
__device__ __half g_Kh[BSTOT * HDIM];
__device__ __half g_Vh[BSTOT * HDIM];
// split-K partials: [b][qtile][half]{ o:64x128, m:64, l:64 }
__device__ float g_Po[NB * NQT * 2 * 64 * HDIM];
__device__ float g_Pm[NB * NQT * 2 * 64];
__device__ float g_Pl[NB * NQT * 2 * 64];

// ------------------- helpers -------------------
// fp16: D += A(16x16, row) * B(16x8, col), fp32 accum
__device__ __forceinline__ void mma16(float* c, const uint32_t* a, const uint32_t* b) {
    asm volatile("mma.sync.aligned.m16n8k16.row.col.f32.f16.f16.f32 "
        "{%0,%1,%2,%3}, {%4,%5,%6,%7}, {%8,%9}, {%0,%1,%2,%3};"
        : "+f"(c[0]), "+f"(c[1]), "+f"(c[2]), "+f"(c[3])
        : "r"(a[0]), "r"(a[1]), "r"(a[2]), "r"(a[3]), "r"(b[0]), "r"(b[1]));
}
__device__ __forceinline__ void ldsm4(uint32_t& r0, uint32_t& r1, uint32_t& r2, uint32_t& r3,
                                      uint32_t addr) {
    asm volatile("ldmatrix.sync.aligned.m8n8.x4.shared.b16 {%0,%1,%2,%3}, [%4];"
        : "=r"(r0), "=r"(r1), "=r"(r2), "=r"(r3) : "r"(addr));
}
__device__ __forceinline__ void ldsm4t(uint32_t& r0, uint32_t& r1, uint32_t& r2, uint32_t& r3,
                                       uint32_t addr) {
    asm volatile("ldmatrix.sync.aligned.m8n8.x4.trans.shared.b16 {%0,%1,%2,%3}, [%4];"
        : "=r"(r0), "=r"(r1), "=r"(r2), "=r"(r3) : "r"(addr));
}
// pack two f32 -> f16x2 (lo = first element)
__device__ __forceinline__ uint32_t ph2(float lo, float hi) {
    uint32_t r; asm("cvt.rn.f16x2.f32 %0, %1, %2;" : "=r"(r) : "f"(hi), "f"(lo)); return r;
}
__device__ __forceinline__ uint32_t smaddr(const void* p) {
    return (uint32_t)__cvta_generic_to_shared(p);
}
__device__ __forceinline__ void cp16(uint32_t s, const void* g) {
    asm volatile("cp.async.ca.shared.global [%0], [%1], 16;" :: "r"(s), "l"(g));
}
__device__ __forceinline__ void cp_commit() {
    asm volatile("cp.async.commit_group;");
}
template <int N>
__device__ __forceinline__ void cp_wait() {
    asm volatile("cp.async.wait_group %0;" :: "n"(N));
}

// ======================= fp32 -> fp16 converts =========================
__global__ __launch_bounds__(256) void convert_X_kernel(const float* __restrict__ X)
{
    size_t i = ((size_t)blockIdx.x * 256 + threadIdx.x) * 8;
    float4 a = *(const float4*)(X + i);
    float4 b = *(const float4*)(X + i + 4);
    uint4 o;
    o.x = ph2(a.x, a.y); o.y = ph2(a.z, a.w);
    o.z = ph2(b.x, b.y); o.w = ph2(b.z, b.w);
    *(uint4*)(g_Xh + i) = o;
}
__global__ __launch_bounds__(256) void convert_W_kernel(
    const float* __restrict__ Wq, const float* __restrict__ Wk,
    const float* __restrict__ Wv)
{
    const float* W = (blockIdx.y == 0) ? Wq : ((blockIdx.y == 1) ? Wk : Wv);
    size_t i = ((size_t)blockIdx.x * 256 + threadIdx.x) * 8;
    float4 a = *(const float4*)(W + i);
    float4 b = *(const float4*)(W + i + 4);
    uint4 o;
    o.x = ph2(a.x, a.y); o.y = ph2(a.z, a.w);
    o.z = ph2(b.x, b.y); o.w = ph2(b.z, b.w);
    *(uint4*)(g_Wh + (size_t)blockIdx.y * DDIM * HDIM + i) = o;
}

// ======================= QKV projection (fp16) =========================
#define PXS 40
#define PWS 136
#define PROJ_SMEM ((2 * 128 * PXS + 2 * 32 * PWS) * 2)   // 37888 B

__global__ __launch_bounds__(256, 2) void proj_kernel()
{
    const int mat = blockIdx.y;
    const __half* Xg = g_Xh;
    const __half* Wg = g_Wh + (size_t)mat * DDIM * HDIM;
    __half*      Outh = (mat == 0) ? g_Qh : ((mat == 1) ? g_Kh : g_Vh);

    extern __shared__ __half psm[];
    __half* Xb = psm;                      // [2][128*PXS]
    __half* Wb = psm + 2 * 128 * PXS;      // [2][32*PWS]

    const int tid  = threadIdx.x;
    const int warp = tid >> 5, lane = tid & 31;
    const int g = lane >> 2, tig = lane & 3;
    const int wm = warp & 3;
    const int wn = warp >> 2;
    const int row0 = blockIdx.x * 128;

    auto issue_stage = [&](int k0, int s) {
        __half* Xd = Xb + s * 128 * PXS;
        __half* Wd = Wb + s * 32 * PWS;
#pragma unroll
        for (int c = tid; c < 512; c += 256) {
            int r = c >> 2, c8 = c & 3;
            cp16(smaddr(Xd + r * PXS + c8 * 8),
                 Xg + (size_t)(row0 + r) * DDIM + k0 + c8 * 8);
        }
#pragma unroll
        for (int c = tid; c < 512; c += 256) {
            int r = c >> 4, c8 = c & 15;
            cp16(smaddr(Wd + r * PWS + c8 * 8),
                 Wg + (size_t)(k0 + r) * HDIM + c8 * 8);
        }
        cp_commit();
    };

    float acc[2][8][4];
#pragma unroll
    for (int mi = 0; mi < 2; mi++)
#pragma unroll
        for (int ni = 0; ni < 8; ni++)
#pragma unroll
            for (int j = 0; j < 4; j++) acc[mi][ni][j] = 0.f;

    issue_stage(0, 0);

    const int a_off = (lane & 15) * PXS + (lane >> 4) * 8;
    const int b_off = lane * PWS;

    for (int ki = 0; ki < 32; ki++) {
        if (ki < 31) { issue_stage((ki + 1) * 32, (ki + 1) & 1); cp_wait<1>(); }
        else         { cp_wait<0>(); }
        __syncthreads();

        const uint32_t XsA = smaddr(Xb + (ki & 1) * 128 * PXS);
        const uint32_t WsA = smaddr(Wb + (ki & 1) * 32 * PWS);

        uint32_t a[2][2][4];
#pragma unroll
        for (int mi = 0; mi < 2; mi++)
#pragma unroll
            for (int kc = 0; kc < 2; kc++) {
                uint32_t addr = XsA + (uint32_t)((wm * 32 + mi * 16) * PXS + kc * 16 + a_off) * 2;
                ldsm4(a[mi][kc][0], a[mi][kc][1], a[mi][kc][2], a[mi][kc][3], addr);
            }
#pragma unroll
        for (int ni = 0; ni < 8; ni++) {
            uint32_t r0, r1, r2, r3;
            uint32_t addr = WsA + (uint32_t)(b_off + wn * 64 + ni * 8) * 2;
            ldsm4t(r0, r1, r2, r3, addr);
            uint32_t b01[2] = {r0, r1}, b23[2] = {r2, r3};
#pragma unroll
            for (int mi = 0; mi < 2; mi++) {
                mma16(acc[mi][ni], a[mi][0], b01);
                mma16(acc[mi][ni], a[mi][1], b23);
            }
        }
        __syncthreads();
    }

    const float osc = (mat == 0) ? 0.088388347648318447f : 1.0f;
#pragma unroll
    for (int mi = 0; mi < 2; mi++) {
        const int r = row0 + wm * 32 + mi * 16 + g;
#pragma unroll
        for (int ni = 0; ni < 8; ni++) {
            const int c = wn * 64 + ni * 8 + 2 * tig;
            *(uint32_t*)(Outh + (size_t)r       * HDIM + c) =
                ph2(acc[mi][ni][0] * osc, acc[mi][ni][1] * osc);
            *(uint32_t*)(Outh + (size_t)(r + 8) * HDIM + c) =
                ph2(acc[mi][ni][2] * osc, acc[mi][ni][3] * osc);
        }
    }
}

// ======================= flash attention (split-K) ========================
// grid (128, NB): bx -> qtile = 63-(bx>>1), half = bx&1.
// half 0: kt in [0, n0); half 1: kt in [n0, n), n = qtile+1, n0 = (n+1)/2.
// Partial (o, m, l) written to g_Po/g_Pm/g_Pl; merged by merge_kernel.
#define HS 136                       // half-stride per K/V smem row (272 B)
#define ATT_SMEM (4 * 64 * HS * 2)   // 2 K bufs + 2 V bufs = 69632 B

__global__ __launch_bounds__(128) void attn_kernel()
{
    extern __shared__ __half hsm[];
    __half* Kb = hsm;                  // [2][64*HS]
    __half* Vb = hsm + 2 * 64 * HS;    // [2][64*HS]

    const int tid  = threadIdx.x;
    const int warp = tid >> 5, lane = tid & 31;
    const int g = lane >> 2, tig = lane & 3;
    const int rb = warp * 16;
    const int b  = blockIdx.y;

    const __half* Q = g_Qh + (size_t)b * SEQ * HDIM;
    const __half* K = g_Kh + (size_t)b * SEQ * HDIM;
    const __half* V = g_Vh + (size_t)b * SEQ * HDIM;

    const int qtile = 63 - ((int)blockIdx.x >> 1);   // longest first
    const int half  = (int)blockIdx.x & 1;
    const int qbase = qtile * 64;
    const int n  = qtile + 1;
    const int n0 = (n + 1) >> 1;
    const int kt0 = half ? n0 : 0;
    const int kt1 = half ? n  : n0;

    auto issue_stage = [&](int kbase, int s) {
        __half* Kd = Kb + s * 64 * HS;
        __half* Vd = Vb + s * 64 * HS;
#pragma unroll
        for (int c = tid; c < 1024; c += 128) {
            int r = c >> 4, c8 = c & 15;
            cp16(smaddr(Kd + r * HS + c8 * 8),
                 K + (size_t)(kbase + r) * HDIM + c8 * 8);
            cp16(smaddr(Vd + r * HS + c8 * 8),
                 V + (size_t)(kbase + r) * HDIM + c8 * 8);
        }
        cp_commit();
    };

    float o[16][4];
#pragma unroll
    for (int nt = 0; nt < 16; nt++)
#pragma unroll
        for (int j = 0; j < 4; j++) o[nt][j] = 0.f;
    float mr[2] = {-INFINITY, -INFINITY};
    float lr[2] = {0.f, 0.f};

    if (kt0 < kt1) {
        // Q -> register A-fragments (fp16, pre-scaled in gmem)
        uint32_t qa[8][4];
#pragma unroll
        for (int ks = 0; ks < 8; ks++) {
            const __half* q0 = Q + (size_t)(qbase + rb + g)     * HDIM + ks * 16;
            const __half* q1 = Q + (size_t)(qbase + rb + g + 8) * HDIM + ks * 16;
            qa[ks][0] = *(const uint32_t*)(q0 + 2 * tig);
            qa[ks][1] = *(const uint32_t*)(q1 + 2 * tig);
            qa[ks][2] = *(const uint32_t*)(q0 + 2 * tig + 8);
            qa[ks][3] = *(const uint32_t*)(q1 + 2 * tig + 8);
        }

        // ldmatrix per-thread offsets (in halves)
        const int kq_off = (lane & 7) * HS + (lane >> 3) * 8;
        const int vv_off = lane * HS;

        // prologue: 2-deep prefetch
        issue_stage(kt0 * 64, kt0 & 1);
        if (kt0 + 1 < kt1) issue_stage((kt0 + 1) * 64, (kt0 + 1) & 1);
        else               cp_commit();

        for (int kt = kt0; kt < kt1; kt++) {
            cp_wait<1>();
            __syncthreads();

            const uint32_t KsA = smaddr(Kb + (kt & 1) * 64 * HS);
            const uint32_t VsA = smaddr(Vb + (kt & 1) * 64 * HS);

            // -------- S = Q K^T  (16x64 per warp) --------
            float s[8][4];
#pragma unroll
            for (int ni = 0; ni < 8; ni++)
#pragma unroll
                for (int j = 0; j < 4; j++) s[ni][j] = 0.f;

#pragma unroll
            for (int ni = 0; ni < 8; ni++) {
                const uint32_t base = KsA + (uint32_t)(ni * 8 * HS + kq_off) * 2;
#pragma unroll
                for (int kc = 0; kc < 4; kc++) {
                    uint32_t r0, r1, r2, r3;
                    ldsm4(r0, r1, r2, r3, base + kc * 64);
                    uint32_t b01[2] = {r0, r1}, b23[2] = {r2, r3};
                    mma16(s[ni], qa[2 * kc],     b01);
                    mma16(s[ni], qa[2 * kc + 1], b23);
                }
            }

            // -------- causal mask (diagonal tile only) --------
            if (kt == qtile) {
                const int r0l = rb + g, r1l = rb + g + 8;
#pragma unroll
                for (int ni = 0; ni < 8; ni++) {
                    const int c = ni * 8 + 2 * tig;
                    s[ni][0] = (c     <= r0l) ? s[ni][0] : -INFINITY;
                    s[ni][1] = (c + 1 <= r0l) ? s[ni][1] : -INFINITY;
                    s[ni][2] = (c     <= r1l) ? s[ni][2] : -INFINITY;
                    s[ni][3] = (c + 1 <= r1l) ? s[ni][3] : -INFINITY;
                }
            }

            // -------- online softmax (per row-half, quad reduce) --------
#pragma unroll
            for (int h = 0; h < 2; h++) {
                float tm = -INFINITY;
#pragma unroll
                for (int ni = 0; ni < 8; ni++)
                    tm = fmaxf(tm, fmaxf(s[ni][2 * h], s[ni][2 * h + 1]));
                tm = fmaxf(tm, __shfl_xor_sync(0xffffffffu, tm, 1));
                tm = fmaxf(tm, __shfl_xor_sync(0xffffffffu, tm, 2));

                const float mn = fmaxf(mr[h], tm);
                const float alpha = __expf(mr[h] - mn);
                mr[h] = mn;

                float rs = 0.f;
#pragma unroll
                for (int ni = 0; ni < 8; ni++) {
                    float p0 = __expf(s[ni][2 * h]     - mn);
                    float p1 = __expf(s[ni][2 * h + 1] - mn);
                    s[ni][2 * h] = p0; s[ni][2 * h + 1] = p1;
                    rs += p0 + p1;
                }
                rs += __shfl_xor_sync(0xffffffffu, rs, 1);
                rs += __shfl_xor_sync(0xffffffffu, rs, 2);
                lr[h] = lr[h] * alpha + rs;

#pragma unroll
                for (int nt = 0; nt < 16; nt++) {
                    o[nt][2 * h]     *= alpha;
                    o[nt][2 * h + 1] *= alpha;
                }
            }

            // -------- P -> fp16 A-fragments --------
            uint32_t pa[4][4];
#pragma unroll
            for (int js = 0; js < 4; js++) {
                pa[js][0] = ph2(s[2 * js][0],     s[2 * js][1]);
                pa[js][1] = ph2(s[2 * js][2],     s[2 * js][3]);
                pa[js][2] = ph2(s[2 * js + 1][0], s[2 * js + 1][1]);
                pa[js][3] = ph2(s[2 * js + 1][2], s[2 * js + 1][3]);
            }

            // -------- O += P V  (16x128 per warp) --------
#pragma unroll
            for (int nt = 0; nt < 16; nt++) {
                const uint32_t base = VsA + (uint32_t)(vv_off + nt * 8) * 2;
#pragma unroll
                for (int kc = 0; kc < 2; kc++) {
                    uint32_t r0, r1, r2, r3;
                    ldsm4t(r0, r1, r2, r3, base + kc * (32 * HS * 2));
                    uint32_t b01[2] = {r0, r1}, b23[2] = {r2, r3};
                    mma16(o[nt], pa[2 * kc],     b01);
                    mma16(o[nt], pa[2 * kc + 1], b23);
                }
            }

            __syncthreads();
            if (kt + 2 < kt1) issue_stage((kt + 2) * 64, kt & 1);
            else              cp_commit();
        }

        cp_wait<0>();
    }

    // -------- epilogue: write partial (o, m, l) --------
    const size_t pidx = ((size_t)(b * NQT + qtile) * 2 + half);
    float* Po = g_Po + pidx * (64 * HDIM);
#pragma unroll
    for (int nt = 0; nt < 16; nt++) {
        const int c = nt * 8 + 2 * tig;
        *(float2*)(Po + (rb + g)     * HDIM + c) = make_float2(o[nt][0], o[nt][1]);
        *(float2*)(Po + (rb + g + 8) * HDIM + c) = make_float2(o[nt][2], o[nt][3]);
    }
    if (tig == 0) {
        g_Pm[pidx * 64 + rb + g]     = mr[0];
        g_Pm[pidx * 64 + rb + g + 8] = mr[1];
        g_Pl[pidx * 64 + rb + g]     = lr[0];
        g_Pl[pidx * 64 + rb + g + 8] = lr[1];
    }
}

// ======================= split-K merge =========================
// grid (64, NB), 256 threads; combines the two halves of each qtile.
__global__ __launch_bounds__(256) void merge_kernel(float* __restrict__ Out)
{
    const int q = blockIdx.x, b = blockIdx.y;
    const size_t base = (size_t)(b * NQT + q) * 2;
    const float* o0 = g_Po + base * (64 * HDIM);
    const float* o1 = o0 + 64 * HDIM;

    const int t = threadIdx.x;
    const int r  = t >> 2;            // 64 rows, 4 threads per row
    const int c0 = (t & 3) * 32;      // 32 cols per thread

    const float m0 = g_Pm[base * 64 + r], m1 = g_Pm[(base + 1) * 64 + r];
    const float l0 = g_Pl[base * 64 + r], l1 = g_Pl[(base + 1) * 64 + r];
    const float M  = fmaxf(m0, m1);
    const float w0 = __expf(m0 - M), w1 = __expf(m1 - M);
    const float invL = 1.0f / (l0 * w0 + l1 * w1);

    float* O = Out + (size_t)b * SEQ * HDIM + (size_t)(q * 64 + r) * HDIM;
#pragma unroll
    for (int i = 0; i < 32; i += 4) {
        float4 a = *(const float4*)(o0 + r * HDIM + c0 + i);
        float4 bb = *(const float4*)(o1 + r * HDIM + c0 + i);
        float4 res;
        res.x = (a.x * w0 + bb.x * w1) * invL;
        res.y = (a.y * w0 + bb.y * w1) * invL;
        res.z = (a.z * w0 + bb.z * w1) * invL;
        res.w = (a.w * w0 + bb.w * w1) * invL;
        *(float4*)(O + c0 + i) = res;
    }
}

// =========================== launch =============================
extern "C" void kernel_launch(void* const* d_in, const int* in_sizes, int n_in,
                              void* d_out, int out_size)
{
    (void)in_sizes; (void)n_in; (void)out_size;
    const float* X  = (const float*)d_in[0];
    const float* Wq = (const float*)d_in[1];
    const float* Wk = (const float*)d_in[2];
    const float* Wv = (const float*)d_in[3];
    float* Out = (float*)d_out;

    static int attr_set = 0;
    if (!attr_set) {
        cudaFuncSetAttribute(proj_kernel,
                             cudaFuncAttributeMaxDynamicSharedMemorySize,
                             PROJ_SMEM);
        cudaFuncSetAttribute(attn_kernel,
                             cudaFuncAttributeMaxDynamicSharedMemorySize,
                             ATT_SMEM);
        attr_set = 1;
    }

    // fp32 -> fp16 converts
    convert_X_kernel<<<BSTOT * DDIM / (256 * 8), 256>>>(X);
    dim3 wgrid(DDIM * HDIM / (256 * 8), 3);
    convert_W_kernel<<<wgrid, 256>>>(Wq, Wk, Wv);

    // QKV projections (fp16 tensor cores)
    dim3 pgrid(BSTOT / 128, 3);
    proj_kernel<<<pgrid, 256, PROJ_SMEM>>>();

    // Flash attention, split-K halves
    dim3 agrid(128, NB);
    attn_kernel<<<agrid, 128, ATT_SMEM>>>();

    // Merge halves
    dim3 mgrid(NQT, NB);
    merge_kernel<<<mgrid, 256>>>(Out);
}